// round 1
// baseline (speedup 1.0000x reference)
#include <cuda_runtime.h>
#include <cstdint>
#include <cstddef>

#define EPSF 1e-5f

typedef unsigned long long u64;

// ------------------------- packed f32x2 helpers -------------------------
__device__ __forceinline__ u64 pk(float lo, float hi) {
    u64 r; asm("mov.b64 %0, {%1, %2};" : "=l"(r) : "f"(lo), "f"(hi)); return r;
}
__device__ __forceinline__ u64 dupf(float v) { return pk(v, v); }
__device__ __forceinline__ u64 fma2(u64 a, u64 b, u64 c) {
    u64 d; asm("fma.rn.f32x2 %0, %1, %2, %3;" : "=l"(d) : "l"(a), "l"(b), "l"(c)); return d;
}
__device__ __forceinline__ void upk(u64 v, float& lo, float& hi) {
    asm("mov.b64 {%0, %1}, %2;" : "=f"(lo), "=f"(hi) : "l"(v));
}

// ------------------------- scratch (static device) ----------------------
// sizes: S = 32768 positions total (8 batches * 4096)
__device__ float g_mu1[32768], g_rstd1[32768], g_mu2[32768], g_rstd2[32768];
__device__ float g_Wbig1[384 * 768];   // [c][j]: j<256 -> q1 (ln1q folded), j>=256 -> k1|v1 (ln1kv folded)
__device__ float g_Wbig2[256 * 768];   // [c][j]: j<256 -> q2 (ln2q folded), j>=256 -> k2|v2 (ln2kv folded)
__device__ float g_Wscf[384 * 256];    // [c][o] = Wsc[o][c] * bn_g[o]
__device__ float g_colsum1[768], g_bb1[768];
__device__ float g_colsum2[768], g_bb2[768];
__device__ float g_btot[256];
__device__ float g_buf1[(size_t)32768 * 768];  // [s][0:256]=q1, [256:512]=k1, [512:768]=v1
__device__ float g_buf2[(size_t)32768 * 768];  // [s][0:256]=q2, [256:512]=k2, [512:768]=v2
__device__ float g_o1r[(size_t)32768 * 256];
__device__ float g_o1c[(size_t)32768 * 256];
__device__ float g_o2r[(size_t)32768 * 256];
__device__ float g_o2c[(size_t)32768 * 256];

// ------------------------- 1) LN stats ----------------------------------
template<int WHICH>
__global__ void stats_kernel(const float* __restrict__ x) {
    constexpr int C = (WHICH == 0) ? 384 : 256;
    float* mu   = (WHICH == 0) ? g_mu1   : g_mu2;
    float* rstd = (WHICH == 0) ? g_rstd1 : g_rstd2;
    int s = blockIdx.x * 256 + threadIdx.x;   // 0..32767
    int b = s >> 12, p = s & 4095;
    const float* xp = x + ((size_t)b * C) * 4096 + p;
    float sum = 0.f, sq = 0.f;
#pragma unroll 4
    for (int c = 0; c < C; c++) {
        float v = xp[(size_t)c * 4096];
        sum += v; sq += v * v;
    }
    float m = sum * (1.0f / C);
    float var = sq * (1.0f / C) - m * m;
    mu[s] = m;
    rstd[s] = rsqrtf(var + EPSF);
}

// ------------------------- 2) fold LN/BN into weights --------------------
__global__ void fold_w_kernel(const float* __restrict__ Wq1, const float* __restrict__ Wkv1,
                              const float* __restrict__ ln1q_w, const float* __restrict__ ln1kv_w,
                              const float* __restrict__ Wq2, const float* __restrict__ Wkv2,
                              const float* __restrict__ ln2q_w, const float* __restrict__ ln2kv_w,
                              const float* __restrict__ Wsc, const float* __restrict__ bn_gamma,
                              const float* __restrict__ bn_var) {
    int idx = blockIdx.x * 256 + threadIdx.x;
    if (idx < 384 * 768) {
        int c = idx / 768, j = idx % 768;
        g_Wbig1[idx] = (j < 256) ? ln1q_w[c] * Wq1[c * 256 + j]
                                 : ln1kv_w[c] * Wkv1[c * 512 + (j - 256)];
    }
    if (idx < 256 * 768) {
        int c = idx / 768, j = idx % 768;
        g_Wbig2[idx] = (j < 256) ? ln2q_w[c] * Wq2[c * 256 + j]
                                 : ln2kv_w[c] * Wkv2[c * 512 + (j - 256)];
    }
    if (idx < 384 * 256) {
        int c = idx / 256, o = idx % 256;
        float g = bn_gamma[o] * rsqrtf(bn_var[o] + EPSF);
        g_Wscf[idx] = Wsc[o * 384 + c] * g;
    }
}

__global__ void fold_cols_kernel(const float* __restrict__ Wq1, const float* __restrict__ Wkv1,
                                 const float* __restrict__ ln1q_b, const float* __restrict__ ln1kv_b,
                                 const float* __restrict__ Wq2, const float* __restrict__ Wkv2,
                                 const float* __restrict__ ln2q_b, const float* __restrict__ ln2kv_b,
                                 const float* __restrict__ bout1, const float* __restrict__ bout2,
                                 const float* __restrict__ bn_gamma, const float* __restrict__ bn_beta,
                                 const float* __restrict__ bn_mean, const float* __restrict__ bn_var) {
    int j = blockIdx.x * 256 + threadIdx.x;
    if (j >= 768) return;
    float cs1 = 0.f, b1 = 0.f;
    for (int c = 0; c < 384; c++) {
        cs1 += g_Wbig1[c * 768 + j];
        b1  += (j < 256) ? ln1q_b[c] * Wq1[c * 256 + j]
                         : ln1kv_b[c] * Wkv1[c * 512 + (j - 256)];
    }
    g_colsum1[j] = cs1; g_bb1[j] = b1;
    float cs2 = 0.f, b2 = 0.f;
    for (int c = 0; c < 256; c++) {
        cs2 += g_Wbig2[c * 768 + j];
        b2  += (j < 256) ? ln2q_b[c] * Wq2[c * 256 + j]
                         : ln2kv_b[c] * Wkv2[c * 512 + (j - 256)];
    }
    g_colsum2[j] = cs2; g_bb2[j] = b2;
    if (j < 256) {
        float g = bn_gamma[j] * rsqrtf(bn_var[j] + EPSF);
        g_btot[j] = (bn_beta[j] - bn_mean[j] * g) + bout1[j] + bout2[j];
    }
}

// ------------------------- f32x2 micro-MMA -------------------------------
__device__ __forceinline__ void mma_step(const float (&As)[8][132], const float (&Bs)[8][128],
                                         u64 (&acc)[8][4], int tx, int ty) {
#pragma unroll
    for (int kt = 0; kt < 8; kt++) {
        float4 b0 = *(const float4*)&Bs[kt][tx * 8];
        float4 b1 = *(const float4*)&Bs[kt][tx * 8 + 4];
        u64 bp0 = pk(b0.x, b0.y), bp1 = pk(b0.z, b0.w);
        u64 bp2 = pk(b1.x, b1.y), bp3 = pk(b1.z, b1.w);
#pragma unroll
        for (int i = 0; i < 8; i++) {
            u64 ad = dupf(As[kt][ty * 8 + i]);
            acc[i][0] = fma2(ad, bp0, acc[i][0]);
            acc[i][1] = fma2(ad, bp1, acc[i][1]);
            acc[i][2] = fma2(ad, bp2, acc[i][2]);
            acc[i][3] = fma2(ad, bp3, acc[i][3]);
        }
    }
}

// ------------------------- 3) projection GEMM ----------------------------
// buf[s][j] = rstd[s]*( sum_c x[c][s]*Wf[c][j] - mu[s]*colsum[j] ) + bb[j]
template<int WHICH>
__global__ __launch_bounds__(256)
void proj_gemm_kernel(const float* __restrict__ x) {
    constexpr int K = (WHICH == 0) ? 384 : 256;
    const float* __restrict__ Wf     = (WHICH == 0) ? g_Wbig1   : g_Wbig2;
    const float* __restrict__ colsum = (WHICH == 0) ? g_colsum1 : g_colsum2;
    const float* __restrict__ bb     = (WHICH == 0) ? g_bb1     : g_bb2;
    const float* __restrict__ mu     = (WHICH == 0) ? g_mu1     : g_mu2;
    const float* __restrict__ rstd   = (WHICH == 0) ? g_rstd1   : g_rstd2;
    float* __restrict__ out          = (WHICH == 0) ? g_buf1    : g_buf2;

    __shared__ float As[8][132];
    __shared__ float Bs[8][128];
    const int tid = threadIdx.x;
    const int tx = tid & 15, ty = tid >> 4;
    const int s0 = blockIdx.y * 128;
    const int j0 = blockIdx.x * 128;
    const int b = s0 >> 12, p0 = s0 & 4095;
    const float* xb = x + ((size_t)b * K) * 4096 + p0;

    u64 acc[8][4];
#pragma unroll
    for (int i = 0; i < 8; i++)
#pragma unroll
        for (int j = 0; j < 4; j++) acc[i][j] = 0ULL;

    for (int c0 = 0; c0 < K; c0 += 8) {
#pragma unroll
        for (int i = 0; i < 4; i++) {
            int idx = tid + i * 256;
            int k = idx >> 7, ss = idx & 127;
            As[k][ss] = xb[(size_t)(c0 + k) * 4096 + ss];
            Bs[k][ss] = Wf[(c0 + k) * 768 + j0 + ss];
        }
        __syncthreads();
        mma_step(As, Bs, acc, tx, ty);
        __syncthreads();
    }

    float cs[8], bv[8];
#pragma unroll
    for (int j = 0; j < 8; j++) {
        cs[j] = colsum[j0 + tx * 8 + j];
        bv[j] = bb[j0 + tx * 8 + j];
    }
#pragma unroll
    for (int i = 0; i < 8; i++) {
        int s = s0 + ty * 8 + i;
        float r = rstd[s], m = mu[s];
        float c[8];
#pragma unroll
        for (int jj = 0; jj < 4; jj++) upk(acc[i][jj], c[2 * jj], c[2 * jj + 1]);
        float4 o0, o1;
        o0.x = r * (c[0] - m * cs[0]) + bv[0];
        o0.y = r * (c[1] - m * cs[1]) + bv[1];
        o0.z = r * (c[2] - m * cs[2]) + bv[2];
        o0.w = r * (c[3] - m * cs[3]) + bv[3];
        o1.x = r * (c[4] - m * cs[4]) + bv[4];
        o1.y = r * (c[5] - m * cs[5]) + bv[5];
        o1.z = r * (c[6] - m * cs[6]) + bv[6];
        o1.w = r * (c[7] - m * cs[7]) + bv[7];
        float* op = out + (size_t)s * 768 + j0 + tx * 8;
        *(float4*)op = o0;
        *(float4*)(op + 4) = o1;
    }
}

// ------------------------- 4) axial attention ----------------------------
// block = one (branch, dir, b, head, line); 64 threads, thread t = query t.
__global__ __launch_bounds__(64)
void attn_kernel() {
    __shared__ __align__(16) float Ks[64][32];
    __shared__ __align__(16) float Vs[64][32];
    const int t = threadIdx.x;
    const int line = blockIdx.x;
    const int b = blockIdx.y >> 3, n = blockIdx.y & 7;
    const int br = blockIdx.z >> 1, dir = blockIdx.z & 1;

    const float* Qb  = br ? g_buf2 : g_buf1;
    const float* KVb = br ? g_buf1 : g_buf2;
    float* ob = br ? (dir ? g_o2c : g_o2r) : (dir ? g_o1c : g_o1r);

    // dir 0: row attention over H (i = h, fixed w = line)
    // dir 1: col attention over W (i = w, fixed h = line)
    int s_t = (dir == 0) ? (b * 4096 + t * 64 + line) : (b * 4096 + line * 64 + t);

    const float* qp = Qb  + (size_t)s_t * 768 + n * 32;
    const float* kp = KVb + (size_t)s_t * 768 + 256 + n * 32;
    const float* vp = kp + 256;
#pragma unroll
    for (int d4 = 0; d4 < 8; d4++) {
        *(float4*)&Ks[t][d4 * 4] = *(const float4*)(kp + d4 * 4);
        *(float4*)&Vs[t][d4 * 4] = *(const float4*)(vp + d4 * 4);
    }
    u64 q2[16];
#pragma unroll
    for (int d = 0; d < 16; d++) q2[d] = *(const u64*)(qp + 2 * d);
    __syncthreads();

    float sc[64];
    float smax = -1e30f;
#pragma unroll
    for (int j = 0; j < 64; j++) {
        const u64* k2 = (const u64*)Ks[j];
        u64 a = 0ULL;
#pragma unroll
        for (int d = 0; d < 16; d++) a = fma2(q2[d], k2[d], a);
        float lo, hi; upk(a, lo, hi);
        float v = (lo + hi) * 0.17677669529663687f;  // 1/sqrt(32)
        sc[j] = v;
        smax = fmaxf(smax, v);
    }
    float ssum = 0.f;
#pragma unroll
    for (int j = 0; j < 64; j++) {
        float e = __expf(sc[j] - smax);
        sc[j] = e;
        ssum += e;
    }
    float inv = 1.f / ssum;
    u64 o2[16];
#pragma unroll
    for (int d = 0; d < 16; d++) o2[d] = 0ULL;
#pragma unroll
    for (int j = 0; j < 64; j++) {
        u64 pd = dupf(sc[j]);
        const u64* v2 = (const u64*)Vs[j];
#pragma unroll
        for (int d = 0; d < 16; d++) o2[d] = fma2(pd, v2[d], o2[d]);
    }
    u64 iv = dupf(inv);
    float* op = ob + (size_t)s_t * 256 + n * 32;
#pragma unroll
    for (int d = 0; d < 16; d++) {
        u64 r = fma2(o2[d], iv, 0ULL);
        *(u64*)(op + 2 * d) = r;
    }
}

// ------------------------- 5) final fused GEMM ---------------------------
// out[b][o][p] = x1f@Wscf + (o1r+o1c)@Wout1 + (o2r+o2c)@Wout2 + btot[o] + x2[b][o][p]
__global__ __launch_bounds__(256)
void final_gemm_kernel(const float* __restrict__ x1, const float* __restrict__ x2,
                       const float* __restrict__ Wout1, const float* __restrict__ Wout2,
                       float* __restrict__ out) {
    __shared__ float As[8][132];
    __shared__ float Bs[8][128];
    const int tid = threadIdx.x;
    const int tx = tid & 15, ty = tid >> 4;
    const int s0 = blockIdx.y * 128;
    const int j0 = blockIdx.x * 128;
    const int b = s0 >> 12, p0 = s0 & 4095;

    u64 acc[8][4];
#pragma unroll
    for (int i = 0; i < 8; i++)
#pragma unroll
        for (int j = 0; j < 4; j++) acc[i][j] = 0ULL;

    // Phase A: shortcut conv, A = x1 (NCHW is K-major), K = 384
    {
        const float* xb = x1 + ((size_t)b * 384) * 4096 + p0;
        for (int c0 = 0; c0 < 384; c0 += 8) {
#pragma unroll
            for (int i = 0; i < 4; i++) {
                int idx = tid + i * 256;
                int k = idx >> 7, ss = idx & 127;
                As[k][ss] = xb[(size_t)(c0 + k) * 4096 + ss];
                Bs[k][ss] = g_Wscf[(c0 + k) * 256 + j0 + ss];
            }
            __syncthreads();
            mma_step(As, Bs, acc, tx, ty);
            __syncthreads();
        }
    }
    // Phase B: (o1r+o1c) @ Wout1, K = 256 (row-major A -> transpose into smem)
    {
        int sl = tid >> 1, kq = (tid & 1) * 4;
        for (int c0 = 0; c0 < 256; c0 += 8) {
            {
                const float* pr = g_o1r + (size_t)(s0 + sl) * 256 + c0 + kq;
                const float* pc = g_o1c + (size_t)(s0 + sl) * 256 + c0 + kq;
                float4 a = *(const float4*)pr;
                float4 c = *(const float4*)pc;
                As[kq + 0][sl] = a.x + c.x;
                As[kq + 1][sl] = a.y + c.y;
                As[kq + 2][sl] = a.z + c.z;
                As[kq + 3][sl] = a.w + c.w;
            }
#pragma unroll
            for (int i = 0; i < 4; i++) {
                int idx = tid + i * 256;
                int k = idx >> 7, jj = idx & 127;
                Bs[k][jj] = Wout1[(c0 + k) * 256 + j0 + jj];
            }
            __syncthreads();
            mma_step(As, Bs, acc, tx, ty);
            __syncthreads();
        }
    }
    // Phase C: (o2r+o2c) @ Wout2, K = 256
    {
        int sl = tid >> 1, kq = (tid & 1) * 4;
        for (int c0 = 0; c0 < 256; c0 += 8) {
            {
                const float* pr = g_o2r + (size_t)(s0 + sl) * 256 + c0 + kq;
                const float* pc = g_o2c + (size_t)(s0 + sl) * 256 + c0 + kq;
                float4 a = *(const float4*)pr;
                float4 c = *(const float4*)pc;
                As[kq + 0][sl] = a.x + c.x;
                As[kq + 1][sl] = a.y + c.y;
                As[kq + 2][sl] = a.z + c.z;
                As[kq + 3][sl] = a.w + c.w;
            }
#pragma unroll
            for (int i = 0; i < 4; i++) {
                int idx = tid + i * 256;
                int k = idx >> 7, jj = idx & 127;
                Bs[k][jj] = Wout2[(c0 + k) * 256 + j0 + jj];
            }
            __syncthreads();
            mma_step(As, Bs, acc, tx, ty);
            __syncthreads();
        }
    }

    // epilogue: unpack, add bias + x2 residual, store NCHW (coalesced along p)
    float cf[8][8];
#pragma unroll
    for (int i = 0; i < 8; i++)
#pragma unroll
        for (int jj = 0; jj < 4; jj++) upk(acc[i][jj], cf[i][2 * jj], cf[i][2 * jj + 1]);

#pragma unroll
    for (int j = 0; j < 8; j++) {
        int o = j0 + tx * 8 + j;
        size_t base = ((size_t)(b * 256 + o)) * 4096 + p0 + ty * 8;
        float bt = g_btot[o];
        float4 xa = *(const float4*)(x2 + base);
        float4 xb4 = *(const float4*)(x2 + base + 4);
        float4 r0, r1;
        r0.x = cf[0][j] + bt + xa.x;
        r0.y = cf[1][j] + bt + xa.y;
        r0.z = cf[2][j] + bt + xa.z;
        r0.w = cf[3][j] + bt + xa.w;
        r1.x = cf[4][j] + bt + xb4.x;
        r1.y = cf[5][j] + bt + xb4.y;
        r1.z = cf[6][j] + bt + xb4.z;
        r1.w = cf[7][j] + bt + xb4.w;
        *(float4*)(out + base) = r0;
        *(float4*)(out + base + 4) = r1;
    }
}

// ------------------------- launch ---------------------------------------
extern "C" void kernel_launch(void* const* d_in, const int* in_sizes, int n_in,
                              void* d_out, int out_size) {
    (void)in_sizes; (void)n_in; (void)out_size;
    const float* x1      = (const float*)d_in[0];
    const float* x2      = (const float*)d_in[1];
    const float* ln1q_w  = (const float*)d_in[2];
    const float* ln1q_b  = (const float*)d_in[3];
    const float* ln2kv_w = (const float*)d_in[4];
    const float* ln2kv_b = (const float*)d_in[5];
    const float* Wq1     = (const float*)d_in[6];
    const float* Wkv2    = (const float*)d_in[7];
    const float* Wout1   = (const float*)d_in[8];
    const float* bout1   = (const float*)d_in[9];
    const float* ln2q_w  = (const float*)d_in[10];
    const float* ln2q_b  = (const float*)d_in[11];
    const float* ln1kv_w = (const float*)d_in[12];
    const float* ln1kv_b = (const float*)d_in[13];
    const float* Wq2     = (const float*)d_in[14];
    const float* Wkv1    = (const float*)d_in[15];
    const float* Wout2   = (const float*)d_in[16];
    const float* bout2   = (const float*)d_in[17];
    const float* Wsc     = (const float*)d_in[18];
    const float* bn_g    = (const float*)d_in[19];
    const float* bn_b    = (const float*)d_in[20];
    const float* bn_m    = (const float*)d_in[21];
    const float* bn_v    = (const float*)d_in[22];
    float* out = (float*)d_out;

    stats_kernel<0><<<128, 256>>>(x1);
    stats_kernel<1><<<128, 256>>>(x2);
    fold_w_kernel<<<1152, 256>>>(Wq1, Wkv1, ln1q_w, ln1kv_w,
                                 Wq2, Wkv2, ln2q_w, ln2kv_w,
                                 Wsc, bn_g, bn_v);
    fold_cols_kernel<<<3, 256>>>(Wq1, Wkv1, ln1q_b, ln1kv_b,
                                 Wq2, Wkv2, ln2q_b, ln2kv_b,
                                 bout1, bout2, bn_g, bn_b, bn_m, bn_v);
    proj_gemm_kernel<0><<<dim3(6, 256), 256>>>(x1);
    proj_gemm_kernel<1><<<dim3(6, 256), 256>>>(x2);
    attn_kernel<<<dim3(64, 64, 4), 64>>>();
    final_gemm_kernel<<<dim3(2, 256), 256>>>(x1, x2, Wout1, Wout2, out);
}

// round 3
// speedup vs baseline: 1.0116x; 1.0116x over previous
#include <cuda_runtime.h>
#include <cstdint>
#include <cstddef>

#define EPSF 1e-5f

typedef unsigned long long u64;

// ------------------------- packed f32x2 helpers -------------------------
__device__ __forceinline__ u64 pk(float lo, float hi) {
    u64 r; asm("mov.b64 %0, {%1, %2};" : "=l"(r) : "f"(lo), "f"(hi)); return r;
}
__device__ __forceinline__ u64 dupf(float v) { return pk(v, v); }
__device__ __forceinline__ u64 fma2(u64 a, u64 b, u64 c) {
    u64 d; asm("fma.rn.f32x2 %0, %1, %2, %3;" : "=l"(d) : "l"(a), "l"(b), "l"(c)); return d;
}
__device__ __forceinline__ void upk(u64 v, float& lo, float& hi) {
    asm("mov.b64 {%0, %1}, %2;" : "=f"(lo), "=f"(hi) : "l"(v));
}

// ------------------------- scratch (static device) ----------------------
__device__ float g_mu1[32768], g_rstd1[32768], g_mu2[32768], g_rstd2[32768];
__device__ float g_Wbig1[384 * 768];   // [c][j]: j<256 -> q1 (ln1q folded), j>=256 -> k1|v1 (ln1kv folded)
__device__ float g_Wbig2[256 * 768];   // [c][j]: j<256 -> q2 (ln2q folded), j>=256 -> k2|v2 (ln2kv folded)
__device__ float g_Wscf[384 * 256];    // [c][o] = Wsc[o][c] * bn_g[o]*rsqrt(var)
__device__ float g_colsum1[768], g_bb1[768];
__device__ float g_colsum2[768], g_bb2[768];
__device__ float g_btot[256];
__device__ float g_buf1[(size_t)32768 * 768];  // [s][0:256]=q1, [256:512]=k1, [512:768]=v1
__device__ float g_buf2[(size_t)32768 * 768];
__device__ float g_o1r[(size_t)32768 * 256];
__device__ float g_o1c[(size_t)32768 * 256];
__device__ float g_o2r[(size_t)32768 * 256];
__device__ float g_o2c[(size_t)32768 * 256];

// ------------------------- 1) LN stats ----------------------------------
template<int WHICH>
__global__ void stats_kernel(const float* __restrict__ x) {
    constexpr int C = (WHICH == 0) ? 384 : 256;
    float* mu   = (WHICH == 0) ? g_mu1   : g_mu2;
    float* rstd = (WHICH == 0) ? g_rstd1 : g_rstd2;
    int s = blockIdx.x * 256 + threadIdx.x;   // 0..32767
    int b = s >> 12, p = s & 4095;
    const float* xp = x + ((size_t)b * C) * 4096 + p;
    float sum = 0.f, sq = 0.f;
#pragma unroll 8
    for (int c = 0; c < C; c++) {
        float v = xp[(size_t)c * 4096];
        sum += v; sq += v * v;
    }
    float m = sum * (1.0f / C);
    float var = sq * (1.0f / C) - m * m;
    mu[s] = m;
    rstd[s] = rsqrtf(var + EPSF);
}

// ------------------------- 2) fold LN/BN into weights --------------------
__global__ void fold_w_kernel(const float* __restrict__ Wq1, const float* __restrict__ Wkv1,
                              const float* __restrict__ ln1q_w, const float* __restrict__ ln1kv_w,
                              const float* __restrict__ Wq2, const float* __restrict__ Wkv2,
                              const float* __restrict__ ln2q_w, const float* __restrict__ ln2kv_w,
                              const float* __restrict__ Wsc, const float* __restrict__ bn_gamma,
                              const float* __restrict__ bn_var) {
    int idx = blockIdx.x * 256 + threadIdx.x;
    if (idx < 384 * 768) {
        int c = idx / 768, j = idx % 768;
        g_Wbig1[idx] = (j < 256) ? ln1q_w[c] * Wq1[c * 256 + j]
                                 : ln1kv_w[c] * Wkv1[c * 512 + (j - 256)];
    }
    if (idx < 256 * 768) {
        int c = idx / 768, j = idx % 768;
        g_Wbig2[idx] = (j < 256) ? ln2q_w[c] * Wq2[c * 256 + j]
                                 : ln2kv_w[c] * Wkv2[c * 512 + (j - 256)];
    }
    if (idx < 384 * 256) {
        int c = idx / 256, o = idx % 256;
        float g = bn_gamma[o] * rsqrtf(bn_var[o] + EPSF);
        g_Wscf[idx] = Wsc[o * 384 + c] * g;
    }
}

// parallel fold_cols: one block per j, 128 threads reduce over c
__global__ __launch_bounds__(128)
void fold_cols_kernel(const float* __restrict__ Wq1, const float* __restrict__ Wkv1,
                      const float* __restrict__ ln1q_b, const float* __restrict__ ln1kv_b,
                      const float* __restrict__ Wq2, const float* __restrict__ Wkv2,
                      const float* __restrict__ ln2q_b, const float* __restrict__ ln2kv_b,
                      const float* __restrict__ bout1, const float* __restrict__ bout2,
                      const float* __restrict__ bn_gamma, const float* __restrict__ bn_beta,
                      const float* __restrict__ bn_mean, const float* __restrict__ bn_var) {
    int j = blockIdx.x;     // 0..767
    int t = threadIdx.x;    // 0..127
    float cs1 = 0.f, b1 = 0.f;
    for (int c = t; c < 384; c += 128) {
        cs1 += g_Wbig1[c * 768 + j];
        b1  += (j < 256) ? ln1q_b[c] * Wq1[c * 256 + j]
                         : ln1kv_b[c] * Wkv1[c * 512 + (j - 256)];
    }
    float cs2 = 0.f, b2 = 0.f;
    for (int c = t; c < 256; c += 128) {
        cs2 += g_Wbig2[c * 768 + j];
        b2  += (j < 256) ? ln2q_b[c] * Wq2[c * 256 + j]
                         : ln2kv_b[c] * Wkv2[c * 512 + (j - 256)];
    }
    __shared__ float red[4][128];
    red[0][t] = cs1; red[1][t] = b1; red[2][t] = cs2; red[3][t] = b2;
    __syncthreads();
#pragma unroll
    for (int s = 64; s > 0; s >>= 1) {
        if (t < s) {
#pragma unroll
            for (int v = 0; v < 4; v++) red[v][t] += red[v][t + s];
        }
        __syncthreads();
    }
    if (t == 0) {
        g_colsum1[j] = red[0][0];
        g_bb1[j]     = red[1][0];
        g_colsum2[j] = red[2][0];
        g_bb2[j]     = red[3][0];
        if (j < 256) {
            float g = bn_gamma[j] * rsqrtf(bn_var[j] + EPSF);
            g_btot[j] = (bn_beta[j] - bn_mean[j] * g) + bout1[j] + bout2[j];
        }
    }
}

// ------------------------- f32x2 micro-MMA over 16-deep K-chunk ----------
// Asd: pre-duplicated A (u64 = (v,v)), Bs: raw B. Thread computes 8 rows x 8 cols.
__device__ __forceinline__ void mma16(const u64 (&Asd)[16][130], const float (&Bs)[16][128],
                                      u64 (&acc)[8][4], int tx, int ty) {
#pragma unroll
    for (int kt = 0; kt < 16; kt++) {
        const u64* bp = (const u64*)&Bs[kt][tx * 8];
        u64 b0 = bp[0], b1 = bp[1], b2 = bp[2], b3 = bp[3];
        const u64* ap = &Asd[kt][ty * 8];
        u64 a[8];
#pragma unroll
        for (int i = 0; i < 8; i++) a[i] = ap[i];
#pragma unroll
        for (int i = 0; i < 8; i++) {
            acc[i][0] = fma2(a[i], b0, acc[i][0]);
            acc[i][1] = fma2(a[i], b1, acc[i][1]);
            acc[i][2] = fma2(a[i], b2, acc[i][2]);
            acc[i][3] = fma2(a[i], b3, acc[i][3]);
        }
    }
}

// K-major tile load (source row stride = srcStride floats), writes dup-A + raw-B
__device__ __forceinline__ void load_kmajor(u64 (&Asd)[16][130], float (&Bs)[16][128],
                                            const float* __restrict__ Asrc, size_t aStride,
                                            const float* __restrict__ Bsrc, size_t bStride,
                                            int tid) {
#pragma unroll
    for (int j = 0; j < 2; j++) {
        int lin = tid + j * 256;
        int k = lin >> 5, f4 = lin & 31;
        float4 v = *(const float4*)(Asrc + (size_t)k * aStride + f4 * 4);
        float* dst = (float*)&Asd[k][f4 * 4];
        *(float4*)dst       = make_float4(v.x, v.x, v.y, v.y);
        *(float4*)(dst + 4) = make_float4(v.z, v.z, v.w, v.w);
        float4 wv = *(const float4*)(Bsrc + (size_t)k * bStride + f4 * 4);
        *(float4*)&Bs[k][f4 * 4] = wv;
    }
}

// ------------------------- 3) projection GEMM ----------------------------
template<int WHICH>
__global__ __launch_bounds__(256, 2)
void proj_gemm_kernel(const float* __restrict__ x) {
    constexpr int K = (WHICH == 0) ? 384 : 256;
    const float* __restrict__ Wf     = (WHICH == 0) ? g_Wbig1   : g_Wbig2;
    const float* __restrict__ colsum = (WHICH == 0) ? g_colsum1 : g_colsum2;
    const float* __restrict__ bb     = (WHICH == 0) ? g_bb1     : g_bb2;
    const float* __restrict__ mu     = (WHICH == 0) ? g_mu1     : g_mu2;
    const float* __restrict__ rstd   = (WHICH == 0) ? g_rstd1   : g_rstd2;
    float* __restrict__ out          = (WHICH == 0) ? g_buf1    : g_buf2;

    __shared__ u64 Asd[16][130];
    __shared__ float Bs[16][128];
    const int tid = threadIdx.x;
    const int tx = tid & 15, ty = tid >> 4;
    const int s0 = blockIdx.y * 128;
    const int j0 = blockIdx.x * 128;
    const int b = s0 >> 12, p0 = s0 & 4095;
    const float* xb = x + ((size_t)b * K) * 4096 + p0;

    u64 acc[8][4];
#pragma unroll
    for (int i = 0; i < 8; i++)
#pragma unroll
        for (int j = 0; j < 4; j++) acc[i][j] = 0ULL;

    for (int c0 = 0; c0 < K; c0 += 16) {
        load_kmajor(Asd, Bs, xb + (size_t)c0 * 4096, 4096,
                    Wf + (size_t)c0 * 768 + j0, 768, tid);
        __syncthreads();
        mma16(Asd, Bs, acc, tx, ty);
        __syncthreads();
    }

    float cs[8], bv[8];
#pragma unroll
    for (int j = 0; j < 8; j++) {
        cs[j] = colsum[j0 + tx * 8 + j];
        bv[j] = bb[j0 + tx * 8 + j];
    }
#pragma unroll
    for (int i = 0; i < 8; i++) {
        int s = s0 + ty * 8 + i;
        float r = rstd[s], m = mu[s];
        float c[8];
#pragma unroll
        for (int jj = 0; jj < 4; jj++) upk(acc[i][jj], c[2 * jj], c[2 * jj + 1]);
        float4 o0, o1;
        o0.x = r * (c[0] - m * cs[0]) + bv[0];
        o0.y = r * (c[1] - m * cs[1]) + bv[1];
        o0.z = r * (c[2] - m * cs[2]) + bv[2];
        o0.w = r * (c[3] - m * cs[3]) + bv[3];
        o1.x = r * (c[4] - m * cs[4]) + bv[4];
        o1.y = r * (c[5] - m * cs[5]) + bv[5];
        o1.z = r * (c[6] - m * cs[6]) + bv[6];
        o1.w = r * (c[7] - m * cs[7]) + bv[7];
        float* op = out + (size_t)s * 768 + j0 + tx * 8;
        *(float4*)op = o0;
        *(float4*)(op + 4) = o1;
    }
}

// ------------------------- 4) axial attention ----------------------------
__global__ __launch_bounds__(64)
void attn_kernel() {
    __shared__ __align__(16) float Ks[64][32];
    __shared__ __align__(16) float Vs[64][32];
    const int t = threadIdx.x;
    const int line = blockIdx.x;
    const int b = blockIdx.y >> 3, n = blockIdx.y & 7;
    const int br = blockIdx.z >> 1, dir = blockIdx.z & 1;

    const float* Qb  = br ? g_buf2 : g_buf1;
    const float* KVb = br ? g_buf1 : g_buf2;
    float* ob = br ? (dir ? g_o2c : g_o2r) : (dir ? g_o1c : g_o1r);

    int s_t = (dir == 0) ? (b * 4096 + t * 64 + line) : (b * 4096 + line * 64 + t);

    const float* qp = Qb  + (size_t)s_t * 768 + n * 32;
    const float* kp = KVb + (size_t)s_t * 768 + 256 + n * 32;
    const float* vp = kp + 256;
#pragma unroll
    for (int d4 = 0; d4 < 8; d4++) {
        *(float4*)&Ks[t][d4 * 4] = *(const float4*)(kp + d4 * 4);
        *(float4*)&Vs[t][d4 * 4] = *(const float4*)(vp + d4 * 4);
    }
    u64 q2[16];
#pragma unroll
    for (int d = 0; d < 16; d++) q2[d] = *(const u64*)(qp + 2 * d);
    __syncthreads();

    float sc[64];
    float smax = -1e30f;
#pragma unroll
    for (int j = 0; j < 64; j++) {
        const u64* k2 = (const u64*)Ks[j];
        u64 a = 0ULL;
#pragma unroll
        for (int d = 0; d < 16; d++) a = fma2(q2[d], k2[d], a);
        float lo, hi; upk(a, lo, hi);
        float v = (lo + hi) * 0.17677669529663687f;  // 1/sqrt(32)
        sc[j] = v;
        smax = fmaxf(smax, v);
    }
    float ssum = 0.f;
#pragma unroll
    for (int j = 0; j < 64; j++) {
        float e = __expf(sc[j] - smax);
        sc[j] = e;
        ssum += e;
    }
    float inv = 1.f / ssum;
    u64 o2[16];
#pragma unroll
    for (int d = 0; d < 16; d++) o2[d] = 0ULL;
#pragma unroll
    for (int j = 0; j < 64; j++) {
        u64 pd = dupf(sc[j]);
        const u64* v2 = (const u64*)Vs[j];
#pragma unroll
        for (int d = 0; d < 16; d++) o2[d] = fma2(pd, v2[d], o2[d]);
    }
    u64 iv = dupf(inv);
    float* op = ob + (size_t)s_t * 256 + n * 32;
#pragma unroll
    for (int d = 0; d < 16; d++) {
        u64 r = fma2(o2[d], iv, 0ULL);
        *(u64*)(op + 2 * d) = r;
    }
}

// ------------------------- 5) final fused GEMM ---------------------------
__global__ __launch_bounds__(256, 2)
void final_gemm_kernel(const float* __restrict__ x1, const float* __restrict__ x2,
                       const float* __restrict__ Wout1, const float* __restrict__ Wout2,
                       float* __restrict__ out) {
    __shared__ u64 Asd[16][130];
    __shared__ float Bs[16][128];
    const int tid = threadIdx.x;
    const int tx = tid & 15, ty = tid >> 4;
    const int s0 = blockIdx.y * 128;
    const int j0 = blockIdx.x * 128;
    const int b = s0 >> 12, p0 = s0 & 4095;

    u64 acc[8][4];
#pragma unroll
    for (int i = 0; i < 8; i++)
#pragma unroll
        for (int j = 0; j < 4; j++) acc[i][j] = 0ULL;

    // Phase A: shortcut conv, A = x1 (NCHW K-major), K=384
    {
        const float* xb = x1 + ((size_t)b * 384) * 4096 + p0;
        for (int c0 = 0; c0 < 384; c0 += 16) {
            load_kmajor(Asd, Bs, xb + (size_t)c0 * 4096, 4096,
                        g_Wscf + (size_t)c0 * 256 + j0, 256, tid);
            __syncthreads();
            mma16(Asd, Bs, acc, tx, ty);
            __syncthreads();
        }
    }
    // Phase B/C: (o_r + o_c) @ Wout, K=256, A row-major
#pragma unroll
    for (int ph = 0; ph < 2; ph++) {
        const float* o_r = ph ? g_o2r : g_o1r;
        const float* o_c = ph ? g_o2c : g_o1c;
        const float* W   = ph ? Wout2 : Wout1;
        for (int c0 = 0; c0 < 256; c0 += 16) {
#pragma unroll
            for (int j = 0; j < 2; j++) {
                int lin = tid + j * 256;
                int row = lin >> 2, f4 = lin & 3;
                const float* pr = o_r + (size_t)(s0 + row) * 256 + c0 + f4 * 4;
                const float* pc = o_c + (size_t)(s0 + row) * 256 + c0 + f4 * 4;
                float4 a = *(const float4*)pr;
                float4 c = *(const float4*)pc;
                Asd[f4 * 4 + 0][row] = dupf(a.x + c.x);
                Asd[f4 * 4 + 1][row] = dupf(a.y + c.y);
                Asd[f4 * 4 + 2][row] = dupf(a.z + c.z);
                Asd[f4 * 4 + 3][row] = dupf(a.w + c.w);
            }
#pragma unroll
            for (int j = 0; j < 2; j++) {
                int lin = tid + j * 256;
                int k = lin >> 5, f4 = lin & 31;
                float4 wv = *(const float4*)(W + (size_t)(c0 + k) * 256 + j0 + f4 * 4);
                *(float4*)&Bs[k][f4 * 4] = wv;
            }
            __syncthreads();
            mma16(Asd, Bs, acc, tx, ty);
            __syncthreads();
        }
    }

    // epilogue: bias + x2 residual, store NCHW
    float cf[8][8];
#pragma unroll
    for (int i = 0; i < 8; i++)
#pragma unroll
        for (int jj = 0; jj < 4; jj++) upk(acc[i][jj], cf[i][2 * jj], cf[i][2 * jj + 1]);

#pragma unroll
    for (int j = 0; j < 8; j++) {
        int o = j0 + tx * 8 + j;
        size_t base = ((size_t)(b * 256 + o)) * 4096 + p0 + ty * 8;
        float bt = g_btot[o];
        float4 xa  = *(const float4*)(x2 + base);
        float4 xb4 = *(const float4*)(x2 + base + 4);
        float4 r0, r1;
        r0.x = cf[0][j] + bt + xa.x;
        r0.y = cf[1][j] + bt + xa.y;
        r0.z = cf[2][j] + bt + xa.z;
        r0.w = cf[3][j] + bt + xa.w;
        r1.x = cf[4][j] + bt + xb4.x;
        r1.y = cf[5][j] + bt + xb4.y;
        r1.z = cf[6][j] + bt + xb4.z;
        r1.w = cf[7][j] + bt + xb4.w;
        *(float4*)(out + base) = r0;
        *(float4*)(out + base + 4) = r1;
    }
}

// ------------------------- launch ---------------------------------------
extern "C" void kernel_launch(void* const* d_in, const int* in_sizes, int n_in,
                              void* d_out, int out_size) {
    (void)in_sizes; (void)n_in; (void)out_size;
    const float* x1      = (const float*)d_in[0];
    const float* x2      = (const float*)d_in[1];
    const float* ln1q_w  = (const float*)d_in[2];
    const float* ln1q_b  = (const float*)d_in[3];
    const float* ln2kv_w = (const float*)d_in[4];
    const float* ln2kv_b = (const float*)d_in[5];
    const float* Wq1     = (const float*)d_in[6];
    const float* Wkv2    = (const float*)d_in[7];
    const float* Wout1   = (const float*)d_in[8];
    const float* bout1   = (const float*)d_in[9];
    const float* ln2q_w  = (const float*)d_in[10];
    const float* ln2q_b  = (const float*)d_in[11];
    const float* ln1kv_w = (const float*)d_in[12];
    const float* ln1kv_b = (const float*)d_in[13];
    const float* Wq2     = (const float*)d_in[14];
    const float* Wkv1    = (const float*)d_in[15];
    const float* Wout2   = (const float*)d_in[16];
    const float* bout2   = (const float*)d_in[17];
    const float* Wsc     = (const float*)d_in[18];
    const float* bn_g    = (const float*)d_in[19];
    const float* bn_b    = (const float*)d_in[20];
    const float* bn_m    = (const float*)d_in[21];
    const float* bn_v    = (const float*)d_in[22];
    float* out = (float*)d_out;

    stats_kernel<0><<<128, 256>>>(x1);
    stats_kernel<1><<<128, 256>>>(x2);
    fold_w_kernel<<<1152, 256>>>(Wq1, Wkv1, ln1q_w, ln1kv_w,
                                 Wq2, Wkv2, ln2q_w, ln2kv_w,
                                 Wsc, bn_g, bn_v);
    fold_cols_kernel<<<768, 128>>>(Wq1, Wkv1, ln1q_b, ln1kv_b,
                                   Wq2, Wkv2, ln2q_b, ln2kv_b,
                                   bout1, bout2, bn_g, bn_b, bn_m, bn_v);
    proj_gemm_kernel<0><<<dim3(6, 256), 256>>>(x1);
    proj_gemm_kernel<1><<<dim3(6, 256), 256>>>(x2);
    attn_kernel<<<dim3(64, 64, 4), 64>>>();
    final_gemm_kernel<<<dim3(2, 256), 256>>>(x1, x2, Wout1, Wout2, out);
}

// round 6
// speedup vs baseline: 1.0628x; 1.0507x over previous
#include <cuda_runtime.h>
#include <cstdint>
#include <cstddef>

#define EPSF 1e-5f

typedef unsigned long long u64;

// ------------------------- packed f32x2 helpers -------------------------
__device__ __forceinline__ u64 pk(float lo, float hi) {
    u64 r; asm("mov.b64 %0, {%1, %2};" : "=l"(r) : "f"(lo), "f"(hi)); return r;
}
__device__ __forceinline__ u64 dupf(float v) { return pk(v, v); }
__device__ __forceinline__ u64 fma2(u64 a, u64 b, u64 c) {
    u64 d; asm("fma.rn.f32x2 %0, %1, %2, %3;" : "=l"(d) : "l"(a), "l"(b), "l"(c)); return d;
}
__device__ __forceinline__ void upk(u64 v, float& lo, float& hi) {
    asm("mov.b64 {%0, %1}, %2;" : "=f"(lo), "=f"(hi) : "l"(v));
}

// ------------------------- cp.async helpers ------------------------------
__device__ __forceinline__ uint32_t smem_u32(const void* p) {
    uint32_t a;
    asm("{ .reg .u64 t; cvta.to.shared.u64 t, %1; cvt.u32.u64 %0, t; }" : "=r"(a) : "l"(p));
    return a;
}
__device__ __forceinline__ void cp_async16(uint32_t dst, const void* src) {
    asm volatile("cp.async.cg.shared.global [%0], [%1], 16;" :: "r"(dst), "l"(src) : "memory");
}
#define CP_COMMIT() asm volatile("cp.async.commit_group;" ::: "memory")
#define CP_WAIT0()  asm volatile("cp.async.wait_group 0;" ::: "memory")

// ------------------------- scratch (static device) ----------------------
__device__ float g_mu1[32768], g_rstd1[32768], g_mu2[32768], g_rstd2[32768];
__device__ float g_Wbig1[384 * 768];   // [c][j]: j<256 -> q1, j>=256 -> k1|v1 (LN w folded)
__device__ float g_Wbig2[256 * 768];
__device__ float g_Wscf[384 * 256];    // [c][o] = Wsc[o][c] * bn_g[o]*rsqrt(var)
__device__ float g_colsum1[768], g_bb1[768];
__device__ float g_colsum2[768], g_bb2[768];
__device__ float g_btot[256];
__device__ float g_buf1[(size_t)32768 * 768];  // [s][0:256]=q1, [256:512]=k1, [512:768]=v1
__device__ float g_buf2[(size_t)32768 * 768];
__device__ float g_o1r[(size_t)32768 * 256];
__device__ float g_o1c[(size_t)32768 * 256];
__device__ float g_o2r[(size_t)32768 * 256];
__device__ float g_o2c[(size_t)32768 * 256];

// ------------------------- 1) LN stats ----------------------------------
template<int WHICH>
__global__ void stats_kernel(const float* __restrict__ x) {
    constexpr int C = (WHICH == 0) ? 384 : 256;
    float* mu   = (WHICH == 0) ? g_mu1   : g_mu2;
    float* rstd = (WHICH == 0) ? g_rstd1 : g_rstd2;
    int s = blockIdx.x * 256 + threadIdx.x;
    int b = s >> 12, p = s & 4095;
    const float* xp = x + ((size_t)b * C) * 4096 + p;
    float sum = 0.f, sq = 0.f;
#pragma unroll 8
    for (int c = 0; c < C; c++) {
        float v = xp[(size_t)c * 4096];
        sum += v; sq += v * v;
    }
    float m = sum * (1.0f / C);
    float var = sq * (1.0f / C) - m * m;
    mu[s] = m;
    rstd[s] = rsqrtf(var + EPSF);
}

// ------------------------- 2) fold LN/BN into weights --------------------
__global__ void fold_w_kernel(const float* __restrict__ Wq1, const float* __restrict__ Wkv1,
                              const float* __restrict__ ln1q_w, const float* __restrict__ ln1kv_w,
                              const float* __restrict__ Wq2, const float* __restrict__ Wkv2,
                              const float* __restrict__ ln2q_w, const float* __restrict__ ln2kv_w,
                              const float* __restrict__ Wsc, const float* __restrict__ bn_gamma,
                              const float* __restrict__ bn_var) {
    int idx = blockIdx.x * 256 + threadIdx.x;
    if (idx < 384 * 768) {
        int c = idx / 768, j = idx % 768;
        g_Wbig1[idx] = (j < 256) ? ln1q_w[c] * Wq1[c * 256 + j]
                                 : ln1kv_w[c] * Wkv1[c * 512 + (j - 256)];
    }
    if (idx < 256 * 768) {
        int c = idx / 768, j = idx % 768;
        g_Wbig2[idx] = (j < 256) ? ln2q_w[c] * Wq2[c * 256 + j]
                                 : ln2kv_w[c] * Wkv2[c * 512 + (j - 256)];
    }
    if (idx < 384 * 256) {
        int c = idx / 256, o = idx % 256;
        float g = bn_gamma[o] * rsqrtf(bn_var[o] + EPSF);
        g_Wscf[idx] = Wsc[o * 384 + c] * g;
    }
}

__global__ __launch_bounds__(128)
void fold_cols_kernel(const float* __restrict__ Wq1, const float* __restrict__ Wkv1,
                      const float* __restrict__ ln1q_b, const float* __restrict__ ln1kv_b,
                      const float* __restrict__ Wq2, const float* __restrict__ Wkv2,
                      const float* __restrict__ ln2q_b, const float* __restrict__ ln2kv_b,
                      const float* __restrict__ bout1, const float* __restrict__ bout2,
                      const float* __restrict__ bn_gamma, const float* __restrict__ bn_beta,
                      const float* __restrict__ bn_mean, const float* __restrict__ bn_var) {
    int j = blockIdx.x;
    int t = threadIdx.x;
    float cs1 = 0.f, b1 = 0.f;
    for (int c = t; c < 384; c += 128) {
        cs1 += g_Wbig1[c * 768 + j];
        b1  += (j < 256) ? ln1q_b[c] * Wq1[c * 256 + j]
                         : ln1kv_b[c] * Wkv1[c * 512 + (j - 256)];
    }
    float cs2 = 0.f, b2 = 0.f;
    for (int c = t; c < 256; c += 128) {
        cs2 += g_Wbig2[c * 768 + j];
        b2  += (j < 256) ? ln2q_b[c] * Wq2[c * 256 + j]
                         : ln2kv_b[c] * Wkv2[c * 512 + (j - 256)];
    }
    __shared__ float red[4][128];
    red[0][t] = cs1; red[1][t] = b1; red[2][t] = cs2; red[3][t] = b2;
    __syncthreads();
#pragma unroll
    for (int s = 64; s > 0; s >>= 1) {
        if (t < s) {
#pragma unroll
            for (int v = 0; v < 4; v++) red[v][t] += red[v][t + s];
        }
        __syncthreads();
    }
    if (t == 0) {
        g_colsum1[j] = red[0][0];
        g_bb1[j]     = red[1][0];
        g_colsum2[j] = red[2][0];
        g_bb2[j]     = red[3][0];
        if (j < 256) {
            float g = bn_gamma[j] * rsqrtf(bn_var[j] + EPSF);
            g_btot[j] = (bn_beta[j] - bn_mean[j] * g) + bout1[j] + bout2[j];
        }
    }
}

// ------------------------- f32x2 micro-MMA over 16-deep K-chunk ----------
__device__ __forceinline__ void mma16(const u64 (*As)[130], const float (*Bs)[128],
                                      u64 (&acc)[8][4], int tx, int ty) {
#pragma unroll
    for (int kt = 0; kt < 16; kt++) {
        const u64* bp = (const u64*)&Bs[kt][tx * 8];
        u64 b0 = bp[0], b1 = bp[1], b2 = bp[2], b3 = bp[3];
        const u64* ap = &As[kt][ty * 8];
        u64 a[8];
#pragma unroll
        for (int i = 0; i < 8; i++) a[i] = ap[i];
#pragma unroll
        for (int i = 0; i < 8; i++) {
            acc[i][0] = fma2(a[i], b0, acc[i][0]);
            acc[i][1] = fma2(a[i], b1, acc[i][1]);
            acc[i][2] = fma2(a[i], b2, acc[i][2]);
            acc[i][3] = fma2(a[i], b3, acc[i][3]);
        }
    }
}

// dynamic smem layout: Asd u64[2][16][130] @0 (33280 B), Bs float[2][16][128] @33280 (16384 B)
#define SMEM_GEMM_BYTES (2 * 16 * 130 * 8 + 2 * 16 * 128 * 4)
#define BS_OFF (2 * 16 * 130 * 8)

// ------------------------- 3) projection GEMM (pipelined) ---------------
template<int WHICH>
__global__ __launch_bounds__(256, 2)
void proj_gemm_kernel(const float* __restrict__ x) {
    constexpr int K = (WHICH == 0) ? 384 : 256;
    const float* __restrict__ Wf     = (WHICH == 0) ? g_Wbig1   : g_Wbig2;
    const float* __restrict__ colsum = (WHICH == 0) ? g_colsum1 : g_colsum2;
    const float* __restrict__ bb     = (WHICH == 0) ? g_bb1     : g_bb2;
    const float* __restrict__ mu     = (WHICH == 0) ? g_mu1     : g_mu2;
    const float* __restrict__ rstd   = (WHICH == 0) ? g_rstd1   : g_rstd2;
    float* __restrict__ out          = (WHICH == 0) ? g_buf1    : g_buf2;

    extern __shared__ char smem[];
    u64 (*Asd)[16][130] = (u64(*)[16][130])smem;
    float (*Bs)[16][128] = (float(*)[16][128])(smem + BS_OFF);
    const uint32_t sbase = smem_u32(smem);

    const int tid = threadIdx.x;
    const int tx = tid & 15, ty = tid >> 4;
    const int s0 = blockIdx.y * 128;
    const int j0 = blockIdx.x * 128;
    const int b = s0 >> 12, p0 = s0 & 4095;
    const float* xb = x + ((size_t)b * K) * 4096 + p0;

    // staging indices: lin in [0,512): k = lin>>5, f4 = lin&31 (16B granules)
    const int k0 = tid >> 5, f40 = tid & 31;
    const int k1 = (tid + 256) >> 5, f41 = (tid + 256) & 31;

    u64 acc[8][4];
#pragma unroll
    for (int i = 0; i < 8; i++)
#pragma unroll
        for (int j = 0; j < 4; j++) acc[i][j] = 0ULL;

    float4 pa0, pa1;
    // prologue: chunk 0
    pa0 = *(const float4*)(xb + (size_t)k0 * 4096 + f40 * 4);
    pa1 = *(const float4*)(xb + (size_t)k1 * 4096 + f41 * 4);
    cp_async16(sbase + BS_OFF + (k0 * 128 + f40 * 4) * 4, Wf + (size_t)k0 * 768 + j0 + f40 * 4);
    cp_async16(sbase + BS_OFF + (k1 * 128 + f41 * 4) * 4, Wf + (size_t)k1 * 768 + j0 + f41 * 4);
    CP_COMMIT();
    {
        float* d0 = (float*)&Asd[0][k0][f40 * 4];
        *(float4*)d0       = make_float4(pa0.x, pa0.x, pa0.y, pa0.y);
        *(float4*)(d0 + 4) = make_float4(pa0.z, pa0.z, pa0.w, pa0.w);
        float* d1 = (float*)&Asd[0][k1][f41 * 4];
        *(float4*)d1       = make_float4(pa1.x, pa1.x, pa1.y, pa1.y);
        *(float4*)(d1 + 4) = make_float4(pa1.z, pa1.z, pa1.w, pa1.w);
    }

    int buf = 0;
    for (int c0 = 0; c0 < K; c0 += 16, buf ^= 1) {
        CP_WAIT0();
        __syncthreads();
        bool has_next = (c0 + 16 < K);
        if (has_next) {
            const float* xn = xb + (size_t)(c0 + 16) * 4096;
            pa0 = *(const float4*)(xn + (size_t)k0 * 4096 + f40 * 4);
            pa1 = *(const float4*)(xn + (size_t)k1 * 4096 + f41 * 4);
            uint32_t bdst = sbase + BS_OFF + (buf ^ 1) * 8192;
            const float* wn = Wf + (size_t)(c0 + 16) * 768 + j0;
            cp_async16(bdst + (k0 * 128 + f40 * 4) * 4, wn + (size_t)k0 * 768 + f40 * 4);
            cp_async16(bdst + (k1 * 128 + f41 * 4) * 4, wn + (size_t)k1 * 768 + f41 * 4);
            CP_COMMIT();
        }
        mma16(Asd[buf], Bs[buf], acc, tx, ty);
        if (has_next) {
            float* d0 = (float*)&Asd[buf ^ 1][k0][f40 * 4];
            *(float4*)d0       = make_float4(pa0.x, pa0.x, pa0.y, pa0.y);
            *(float4*)(d0 + 4) = make_float4(pa0.z, pa0.z, pa0.w, pa0.w);
            float* d1 = (float*)&Asd[buf ^ 1][k1][f41 * 4];
            *(float4*)d1       = make_float4(pa1.x, pa1.x, pa1.y, pa1.y);
            *(float4*)(d1 + 4) = make_float4(pa1.z, pa1.z, pa1.w, pa1.w);
        }
    }

    float cs[8], bv[8];
#pragma unroll
    for (int j = 0; j < 8; j++) {
        cs[j] = colsum[j0 + tx * 8 + j];
        bv[j] = bb[j0 + tx * 8 + j];
    }
#pragma unroll
    for (int i = 0; i < 8; i++) {
        int s = s0 + ty * 8 + i;
        float r = rstd[s], m = mu[s];
        float c[8];
#pragma unroll
        for (int jj = 0; jj < 4; jj++) upk(acc[i][jj], c[2 * jj], c[2 * jj + 1]);
        float4 o0, o1;
        o0.x = r * (c[0] - m * cs[0]) + bv[0];
        o0.y = r * (c[1] - m * cs[1]) + bv[1];
        o0.z = r * (c[2] - m * cs[2]) + bv[2];
        o0.w = r * (c[3] - m * cs[3]) + bv[3];
        o1.x = r * (c[4] - m * cs[4]) + bv[4];
        o1.y = r * (c[5] - m * cs[5]) + bv[5];
        o1.z = r * (c[6] - m * cs[6]) + bv[6];
        o1.w = r * (c[7] - m * cs[7]) + bv[7];
        float* op = out + (size_t)s * 768 + j0 + tx * 8;
        *(float4*)op = o0;
        *(float4*)(op + 4) = o1;
    }
}

// ------------------------- 4) axial attention ----------------------------
__global__ __launch_bounds__(64)
void attn_kernel() {
    __shared__ __align__(16) float Ks[64][32];
    __shared__ __align__(16) float Vs[64][32];
    const int t = threadIdx.x;
    const int line = blockIdx.x;
    const int b = blockIdx.y >> 3, n = blockIdx.y & 7;
    const int br = blockIdx.z >> 1, dir = blockIdx.z & 1;

    const float* Qb  = br ? g_buf2 : g_buf1;
    const float* KVb = br ? g_buf1 : g_buf2;
    float* ob = br ? (dir ? g_o2c : g_o2r) : (dir ? g_o1c : g_o1r);

    int s_t = (dir == 0) ? (b * 4096 + t * 64 + line) : (b * 4096 + line * 64 + t);

    const float* qp = Qb  + (size_t)s_t * 768 + n * 32;
    const float* kp = KVb + (size_t)s_t * 768 + 256 + n * 32;
    const float* vp = kp + 256;
#pragma unroll
    for (int d4 = 0; d4 < 8; d4++) {
        *(float4*)&Ks[t][d4 * 4] = *(const float4*)(kp + d4 * 4);
        *(float4*)&Vs[t][d4 * 4] = *(const float4*)(vp + d4 * 4);
    }
    u64 q2[16];
#pragma unroll
    for (int d = 0; d < 16; d++) q2[d] = *(const u64*)(qp + 2 * d);
    __syncthreads();

    float sc[64];
    float smax = -1e30f;
#pragma unroll
    for (int j = 0; j < 64; j++) {
        const u64* k2 = (const u64*)Ks[j];
        u64 a = 0ULL;
#pragma unroll
        for (int d = 0; d < 16; d++) a = fma2(q2[d], k2[d], a);
        float lo, hi; upk(a, lo, hi);
        float v = (lo + hi) * 0.17677669529663687f;
        sc[j] = v;
        smax = fmaxf(smax, v);
    }
    float ssum = 0.f;
#pragma unroll
    for (int j = 0; j < 64; j++) {
        float e = __expf(sc[j] - smax);
        sc[j] = e;
        ssum += e;
    }
    float inv = 1.f / ssum;
    u64 o2[16];
#pragma unroll
    for (int d = 0; d < 16; d++) o2[d] = 0ULL;
#pragma unroll
    for (int j = 0; j < 64; j++) {
        u64 pd = dupf(sc[j]);
        const u64* v2 = (const u64*)Vs[j];
#pragma unroll
        for (int d = 0; d < 16; d++) o2[d] = fma2(pd, v2[d], o2[d]);
    }
    u64 iv = dupf(inv);
    float* op = ob + (size_t)s_t * 256 + n * 32;
#pragma unroll
    for (int d = 0; d < 16; d++) {
        u64 r = fma2(o2[d], iv, 0ULL);
        *(u64*)(op + 2 * d) = r;
    }
}

// ------------------------- 5) final fused GEMM (pipelined) ---------------
__global__ __launch_bounds__(256, 2)
void final_gemm_kernel(const float* __restrict__ x1, const float* __restrict__ x2,
                       const float* __restrict__ Wout1, const float* __restrict__ Wout2,
                       float* __restrict__ out) {
    extern __shared__ char smem[];
    u64 (*Asd)[16][130] = (u64(*)[16][130])smem;
    float (*Bs)[16][128] = (float(*)[16][128])(smem + BS_OFF);
    const uint32_t sbase = smem_u32(smem);

    const int tid = threadIdx.x;
    const int tx = tid & 15, ty = tid >> 4;
    const int s0 = blockIdx.y * 128;
    const int j0 = blockIdx.x * 128;
    const int b = s0 >> 12, p0 = s0 & 4095;

    const int k0 = tid >> 5, f40 = tid & 31;
    const int k1 = (tid + 256) >> 5, f41 = (tid + 256) & 31;
    // row-major A staging map (phases B/C)
    const int row0 = tid >> 2, q0 = tid & 3;
    const int row1 = (tid + 256) >> 2, q1 = (tid + 256) & 3;

    u64 acc[8][4];
#pragma unroll
    for (int i = 0; i < 8; i++)
#pragma unroll
        for (int j = 0; j < 4; j++) acc[i][j] = 0ULL;

    int buf = 0;

    // ---------- Phase A: shortcut conv (x1 c-major @ g_Wscf), K = 384 ----
    {
        const float* xb = x1 + ((size_t)b * 384) * 4096 + p0;
        float4 pa0, pa1;
        pa0 = *(const float4*)(xb + (size_t)k0 * 4096 + f40 * 4);
        pa1 = *(const float4*)(xb + (size_t)k1 * 4096 + f41 * 4);
        cp_async16(sbase + BS_OFF + buf * 8192 + (k0 * 128 + f40 * 4) * 4,
                   g_Wscf + (size_t)k0 * 256 + j0 + f40 * 4);
        cp_async16(sbase + BS_OFF + buf * 8192 + (k1 * 128 + f41 * 4) * 4,
                   g_Wscf + (size_t)k1 * 256 + j0 + f41 * 4);
        CP_COMMIT();
        {
            float* d0 = (float*)&Asd[buf][k0][f40 * 4];
            *(float4*)d0       = make_float4(pa0.x, pa0.x, pa0.y, pa0.y);
            *(float4*)(d0 + 4) = make_float4(pa0.z, pa0.z, pa0.w, pa0.w);
            float* d1 = (float*)&Asd[buf][k1][f41 * 4];
            *(float4*)d1       = make_float4(pa1.x, pa1.x, pa1.y, pa1.y);
            *(float4*)(d1 + 4) = make_float4(pa1.z, pa1.z, pa1.w, pa1.w);
        }
        for (int c0 = 0; c0 < 384; c0 += 16, buf ^= 1) {
            CP_WAIT0();
            __syncthreads();
            bool has_next = (c0 + 16 < 384);
            if (has_next) {
                const float* xn = xb + (size_t)(c0 + 16) * 4096;
                pa0 = *(const float4*)(xn + (size_t)k0 * 4096 + f40 * 4);
                pa1 = *(const float4*)(xn + (size_t)k1 * 4096 + f41 * 4);
                uint32_t bdst = sbase + BS_OFF + (buf ^ 1) * 8192;
                const float* wn = g_Wscf + (size_t)(c0 + 16) * 256 + j0;
                cp_async16(bdst + (k0 * 128 + f40 * 4) * 4, wn + (size_t)k0 * 256 + f40 * 4);
                cp_async16(bdst + (k1 * 128 + f41 * 4) * 4, wn + (size_t)k1 * 256 + f41 * 4);
                CP_COMMIT();
            }
            mma16(Asd[buf], Bs[buf], acc, tx, ty);
            if (has_next) {
                float* d0 = (float*)&Asd[buf ^ 1][k0][f40 * 4];
                *(float4*)d0       = make_float4(pa0.x, pa0.x, pa0.y, pa0.y);
                *(float4*)(d0 + 4) = make_float4(pa0.z, pa0.z, pa0.w, pa0.w);
                float* d1 = (float*)&Asd[buf ^ 1][k1][f41 * 4];
                *(float4*)d1       = make_float4(pa1.x, pa1.x, pa1.y, pa1.y);
                *(float4*)(d1 + 4) = make_float4(pa1.z, pa1.z, pa1.w, pa1.w);
            }
        }
    }

    // ---------- Phases B/C: (o_r + o_c) @ Wout, K = 256 each -------------
#pragma unroll
    for (int ph = 0; ph < 2; ph++) {
        const float* o_r = ph ? g_o2r : g_o1r;
        const float* o_c = ph ? g_o2c : g_o1c;
        const float* W   = ph ? Wout2 : Wout1;

        float4 sa0, sa1;
        {
            float4 a = *(const float4*)(o_r + (size_t)(s0 + row0) * 256 + q0 * 4);
            float4 c = *(const float4*)(o_c + (size_t)(s0 + row0) * 256 + q0 * 4);
            sa0 = make_float4(a.x + c.x, a.y + c.y, a.z + c.z, a.w + c.w);
            a = *(const float4*)(o_r + (size_t)(s0 + row1) * 256 + q1 * 4);
            c = *(const float4*)(o_c + (size_t)(s0 + row1) * 256 + q1 * 4);
            sa1 = make_float4(a.x + c.x, a.y + c.y, a.z + c.z, a.w + c.w);
        }
        __syncthreads();  // previous phase readers done before overwriting buf
        cp_async16(sbase + BS_OFF + buf * 8192 + (k0 * 128 + f40 * 4) * 4,
                   W + (size_t)k0 * 256 + j0 + f40 * 4);
        cp_async16(sbase + BS_OFF + buf * 8192 + (k1 * 128 + f41 * 4) * 4,
                   W + (size_t)k1 * 256 + j0 + f41 * 4);
        CP_COMMIT();
        {
            Asd[buf][q0 * 4 + 0][row0] = dupf(sa0.x);
            Asd[buf][q0 * 4 + 1][row0] = dupf(sa0.y);
            Asd[buf][q0 * 4 + 2][row0] = dupf(sa0.z);
            Asd[buf][q0 * 4 + 3][row0] = dupf(sa0.w);
            Asd[buf][q1 * 4 + 0][row1] = dupf(sa1.x);
            Asd[buf][q1 * 4 + 1][row1] = dupf(sa1.y);
            Asd[buf][q1 * 4 + 2][row1] = dupf(sa1.z);
            Asd[buf][q1 * 4 + 3][row1] = dupf(sa1.w);
        }
        for (int c0 = 0; c0 < 256; c0 += 16, buf ^= 1) {
            CP_WAIT0();
            __syncthreads();
            bool has_next = (c0 + 16 < 256);
            if (has_next) {
                int cn = c0 + 16;
                float4 a = *(const float4*)(o_r + (size_t)(s0 + row0) * 256 + cn + q0 * 4);
                float4 c = *(const float4*)(o_c + (size_t)(s0 + row0) * 256 + cn + q0 * 4);
                sa0 = make_float4(a.x + c.x, a.y + c.y, a.z + c.z, a.w + c.w);
                a = *(const float4*)(o_r + (size_t)(s0 + row1) * 256 + cn + q1 * 4);
                c = *(const float4*)(o_c + (size_t)(s0 + row1) * 256 + cn + q1 * 4);
                sa1 = make_float4(a.x + c.x, a.y + c.y, a.z + c.z, a.w + c.w);
                uint32_t bdst = sbase + BS_OFF + (buf ^ 1) * 8192;
                const float* wn = W + (size_t)cn * 256 + j0;
                cp_async16(bdst + (k0 * 128 + f40 * 4) * 4, wn + (size_t)k0 * 256 + f40 * 4);
                cp_async16(bdst + (k1 * 128 + f41 * 4) * 4, wn + (size_t)k1 * 256 + f41 * 4);
                CP_COMMIT();
            }
            mma16(Asd[buf], Bs[buf], acc, tx, ty);
            if (has_next) {
                Asd[buf ^ 1][q0 * 4 + 0][row0] = dupf(sa0.x);
                Asd[buf ^ 1][q0 * 4 + 1][row0] = dupf(sa0.y);
                Asd[buf ^ 1][q0 * 4 + 2][row0] = dupf(sa0.z);
                Asd[buf ^ 1][q0 * 4 + 3][row0] = dupf(sa0.w);
                Asd[buf ^ 1][q1 * 4 + 0][row1] = dupf(sa1.x);
                Asd[buf ^ 1][q1 * 4 + 1][row1] = dupf(sa1.y);
                Asd[buf ^ 1][q1 * 4 + 2][row1] = dupf(sa1.z);
                Asd[buf ^ 1][q1 * 4 + 3][row1] = dupf(sa1.w);
            }
        }
    }

    // epilogue: bias + x2 residual, store NCHW
    float cf[8][8];
#pragma unroll
    for (int i = 0; i < 8; i++)
#pragma unroll
        for (int jj = 0; jj < 4; jj++) upk(acc[i][jj], cf[i][2 * jj], cf[i][2 * jj + 1]);

#pragma unroll
    for (int j = 0; j < 8; j++) {
        int o = j0 + tx * 8 + j;
        size_t base = ((size_t)(b * 256 + o)) * 4096 + p0 + ty * 8;
        float bt = g_btot[o];
        float4 xa  = *(const float4*)(x2 + base);
        float4 xb4 = *(const float4*)(x2 + base + 4);
        float4 r0, r1;
        r0.x = cf[0][j] + bt + xa.x;
        r0.y = cf[1][j] + bt + xa.y;
        r0.z = cf[2][j] + bt + xa.z;
        r0.w = cf[3][j] + bt + xa.w;
        r1.x = cf[4][j] + bt + xb4.x;
        r1.y = cf[5][j] + bt + xb4.y;
        r1.z = cf[6][j] + bt + xb4.z;
        r1.w = cf[7][j] + bt + xb4.w;
        *(float4*)(out + base) = r0;
        *(float4*)(out + base + 4) = r1;
    }
}

// ------------------------- launch ---------------------------------------
extern "C" void kernel_launch(void* const* d_in, const int* in_sizes, int n_in,
                              void* d_out, int out_size) {
    (void)in_sizes; (void)n_in; (void)out_size;
    const float* x1      = (const float*)d_in[0];
    const float* x2      = (const float*)d_in[1];
    const float* ln1q_w  = (const float*)d_in[2];
    const float* ln1q_b  = (const float*)d_in[3];
    const float* ln2kv_w = (const float*)d_in[4];
    const float* ln2kv_b = (const float*)d_in[5];
    const float* Wq1     = (const float*)d_in[6];
    const float* Wkv2    = (const float*)d_in[7];
    const float* Wout1   = (const float*)d_in[8];
    const float* bout1   = (const float*)d_in[9];
    const float* ln2q_w  = (const float*)d_in[10];
    const float* ln2q_b  = (const float*)d_in[11];
    const float* ln1kv_w = (const float*)d_in[12];
    const float* ln1kv_b = (const float*)d_in[13];
    const float* Wq2     = (const float*)d_in[14];
    const float* Wkv1    = (const float*)d_in[15];
    const float* Wout2   = (const float*)d_in[16];
    const float* bout2   = (const float*)d_in[17];
    const float* Wsc     = (const float*)d_in[18];
    const float* bn_g    = (const float*)d_in[19];
    const float* bn_b    = (const float*)d_in[20];
    const float* bn_m    = (const float*)d_in[21];
    const float* bn_v    = (const float*)d_in[22];
    float* out = (float*)d_out;

    cudaFuncSetAttribute(proj_gemm_kernel<0>, cudaFuncAttributeMaxDynamicSharedMemorySize, SMEM_GEMM_BYTES);
    cudaFuncSetAttribute(proj_gemm_kernel<1>, cudaFuncAttributeMaxDynamicSharedMemorySize, SMEM_GEMM_BYTES);
    cudaFuncSetAttribute(final_gemm_kernel,   cudaFuncAttributeMaxDynamicSharedMemorySize, SMEM_GEMM_BYTES);

    stats_kernel<0><<<128, 256>>>(x1);
    stats_kernel<1><<<128, 256>>>(x2);
    fold_w_kernel<<<1152, 256>>>(Wq1, Wkv1, ln1q_w, ln1kv_w,
                                 Wq2, Wkv2, ln2q_w, ln2kv_w,
                                 Wsc, bn_g, bn_v);
    fold_cols_kernel<<<768, 128>>>(Wq1, Wkv1, ln1q_b, ln1kv_b,
                                   Wq2, Wkv2, ln2q_b, ln2kv_b,
                                   bout1, bout2, bn_g, bn_b, bn_m, bn_v);
    proj_gemm_kernel<0><<<dim3(6, 256), 256, SMEM_GEMM_BYTES>>>(x1);
    proj_gemm_kernel<1><<<dim3(6, 256), 256, SMEM_GEMM_BYTES>>>(x2);
    attn_kernel<<<dim3(64, 64, 4), 64>>>();
    final_gemm_kernel<<<dim3(2, 256), 256, SMEM_GEMM_BYTES>>>(x1, x2, Wout1, Wout2, out);
}

// round 8
// speedup vs baseline: 1.0806x; 1.0167x over previous
#include <cuda_runtime.h>
#include <cstdint>
#include <cstddef>

#define EPSF 1e-5f

typedef unsigned long long u64;

// ------------------------- packed f32x2 helpers -------------------------
__device__ __forceinline__ u64 pk(float lo, float hi) {
    u64 r; asm("mov.b64 %0, {%1, %2};" : "=l"(r) : "f"(lo), "f"(hi)); return r;
}
__device__ __forceinline__ u64 dupf(float v) { return pk(v, v); }
__device__ __forceinline__ u64 fma2(u64 a, u64 b, u64 c) {
    u64 d; asm("fma.rn.f32x2 %0, %1, %2, %3;" : "=l"(d) : "l"(a), "l"(b), "l"(c)); return d;
}
__device__ __forceinline__ void upk(u64 v, float& lo, float& hi) {
    asm("mov.b64 {%0, %1}, %2;" : "=f"(lo), "=f"(hi) : "l"(v));
}

// ------------------------- cp.async helpers ------------------------------
__device__ __forceinline__ uint32_t smem_u32(const void* p) {
    uint32_t a;
    asm("{ .reg .u64 t; cvta.to.shared.u64 t, %1; cvt.u32.u64 %0, t; }" : "=r"(a) : "l"(p));
    return a;
}
__device__ __forceinline__ void cp_async16(uint32_t dst, const void* src) {
    asm volatile("cp.async.cg.shared.global [%0], [%1], 16;" :: "r"(dst), "l"(src) : "memory");
}
#define CP_COMMIT() asm volatile("cp.async.commit_group;" ::: "memory")
#define CP_WAIT0()  asm volatile("cp.async.wait_group 0;" ::: "memory")

// ------------------------- scratch (static device) ----------------------
__device__ float g_Wbig1[384 * 768];   // [c][j]: j<256 -> q1, j>=256 -> k1|v1 (LN w folded)
__device__ float g_Wbig2[256 * 768];
__device__ float g_Wscf[384 * 256];    // [c][o] = Wsc[o][c] * bn_g[o]*rsqrt(var)
__device__ float g_colsum1[768], g_bb1[768];
__device__ float g_colsum2[768], g_bb2[768];
__device__ float g_btot[256];
__device__ float g_buf1[(size_t)32768 * 768];  // [s][0:256]=q1, [256:512]=k1, [512:768]=v1
__device__ float g_buf2[(size_t)32768 * 768];
__device__ float g_o1r[(size_t)32768 * 256];
__device__ float g_o1c[(size_t)32768 * 256];
__device__ float g_o2r[(size_t)32768 * 256];
__device__ float g_o2c[(size_t)32768 * 256];

// ------------------------- 1) fold LN/BN into weights --------------------
__global__ void fold_w_kernel(const float* __restrict__ Wq1, const float* __restrict__ Wkv1,
                              const float* __restrict__ ln1q_w, const float* __restrict__ ln1kv_w,
                              const float* __restrict__ Wq2, const float* __restrict__ Wkv2,
                              const float* __restrict__ ln2q_w, const float* __restrict__ ln2kv_w,
                              const float* __restrict__ Wsc, const float* __restrict__ bn_gamma,
                              const float* __restrict__ bn_var) {
    int idx = blockIdx.x * 256 + threadIdx.x;
    if (idx < 384 * 768) {
        int c = idx / 768, j = idx % 768;
        g_Wbig1[idx] = (j < 256) ? ln1q_w[c] * Wq1[c * 256 + j]
                                 : ln1kv_w[c] * Wkv1[c * 512 + (j - 256)];
    }
    if (idx < 256 * 768) {
        int c = idx / 768, j = idx % 768;
        g_Wbig2[idx] = (j < 256) ? ln2q_w[c] * Wq2[c * 256 + j]
                                 : ln2kv_w[c] * Wkv2[c * 512 + (j - 256)];
    }
    if (idx < 384 * 256) {
        int c = idx / 256, o = idx % 256;
        float g = bn_gamma[o] * rsqrtf(bn_var[o] + EPSF);
        g_Wscf[idx] = Wsc[o * 384 + c] * g;
    }
}

__global__ __launch_bounds__(128)
void fold_cols_kernel(const float* __restrict__ Wq1, const float* __restrict__ Wkv1,
                      const float* __restrict__ ln1q_b, const float* __restrict__ ln1kv_b,
                      const float* __restrict__ Wq2, const float* __restrict__ Wkv2,
                      const float* __restrict__ ln2q_b, const float* __restrict__ ln2kv_b,
                      const float* __restrict__ bout1, const float* __restrict__ bout2,
                      const float* __restrict__ bn_gamma, const float* __restrict__ bn_beta,
                      const float* __restrict__ bn_mean, const float* __restrict__ bn_var) {
    int j = blockIdx.x;
    int t = threadIdx.x;
    float cs1 = 0.f, b1 = 0.f;
    for (int c = t; c < 384; c += 128) {
        cs1 += g_Wbig1[c * 768 + j];
        b1  += (j < 256) ? ln1q_b[c] * Wq1[c * 256 + j]
                         : ln1kv_b[c] * Wkv1[c * 512 + (j - 256)];
    }
    float cs2 = 0.f, b2 = 0.f;
    for (int c = t; c < 256; c += 128) {
        cs2 += g_Wbig2[c * 768 + j];
        b2  += (j < 256) ? ln2q_b[c] * Wq2[c * 256 + j]
                         : ln2kv_b[c] * Wkv2[c * 512 + (j - 256)];
    }
    __shared__ float red[4][128];
    red[0][t] = cs1; red[1][t] = b1; red[2][t] = cs2; red[3][t] = b2;
    __syncthreads();
#pragma unroll
    for (int s = 64; s > 0; s >>= 1) {
        if (t < s) {
#pragma unroll
            for (int v = 0; v < 4; v++) red[v][t] += red[v][t + s];
        }
        __syncthreads();
    }
    if (t == 0) {
        g_colsum1[j] = red[0][0];
        g_bb1[j]     = red[1][0];
        g_colsum2[j] = red[2][0];
        g_bb2[j]     = red[3][0];
        if (j < 256) {
            float g = bn_gamma[j] * rsqrtf(bn_var[j] + EPSF);
            g_btot[j] = (bn_beta[j] - bn_mean[j] * g) + bout1[j] + bout2[j];
        }
    }
}

// ------------------------- f32x2 micro-MMA over 16-deep K-chunk ----------
__device__ __forceinline__ void mma16(const u64 (*As)[130], const float (*Bs)[128],
                                      u64 (&acc)[8][4], int tx, int ty) {
#pragma unroll
    for (int kt = 0; kt < 16; kt++) {
        const u64* bp = (const u64*)&Bs[kt][tx * 8];
        u64 b0 = bp[0], b1 = bp[1], b2 = bp[2], b3 = bp[3];
        const u64* ap = &As[kt][ty * 8];
        u64 a[8];
#pragma unroll
        for (int i = 0; i < 8; i++) a[i] = ap[i];
#pragma unroll
        for (int i = 0; i < 8; i++) {
            acc[i][0] = fma2(a[i], b0, acc[i][0]);
            acc[i][1] = fma2(a[i], b1, acc[i][1]);
            acc[i][2] = fma2(a[i], b2, acc[i][2]);
            acc[i][3] = fma2(a[i], b3, acc[i][3]);
        }
    }
}

// dynamic smem layout: Asd u64[2][16][130] @0 (33280 B), Bs float[2][16][128] @33280 (16384 B)
#define SMEM_GEMM_BYTES (2 * 16 * 130 * 8 + 2 * 16 * 128 * 4)
#define BS_OFF (2 * 16 * 130 * 8)

// ------------------------- 2) projection GEMM (pipelined + fused LN stats)
template<int WHICH>
__global__ __launch_bounds__(256, 2)
void proj_gemm_kernel(const float* __restrict__ x) {
    constexpr int K = (WHICH == 0) ? 384 : 256;
    const float* __restrict__ Wf     = (WHICH == 0) ? g_Wbig1   : g_Wbig2;
    const float* __restrict__ colsum = (WHICH == 0) ? g_colsum1 : g_colsum2;
    const float* __restrict__ bb     = (WHICH == 0) ? g_bb1     : g_bb2;
    float* __restrict__ out          = (WHICH == 0) ? g_buf1    : g_buf2;

    extern __shared__ char smem[];
    u64 (*Asd)[16][130] = (u64(*)[16][130])smem;
    float (*Bs)[16][128] = (float(*)[16][128])(smem + BS_OFF);
    const uint32_t sbase = smem_u32(smem);

    const int tid = threadIdx.x;
    const int tx = tid & 15, ty = tid >> 4;
    const int s0 = blockIdx.y * 128;
    const int j0 = blockIdx.x * 128;
    const int b = s0 >> 12, p0 = s0 & 4095;
    const float* xb = x + ((size_t)b * K) * 4096 + p0;

    // staging indices: lin in [0,512): k = lin>>5, f4 = lin&31 (16B granules)
    const int k0 = tid >> 5, f40 = tid & 31;
    const int k1 = k0 + 8, f41 = f40;

    u64 acc[8][4];
#pragma unroll
    for (int i = 0; i < 8; i++)
#pragma unroll
        for (int j = 0; j < 4; j++) acc[i][j] = 0ULL;

    // fused LN stats accumulators (4 spatial cols per thread; channels c ≡ k0 or k0+8 mod 16)
    float asum[4] = {0.f, 0.f, 0.f, 0.f};
    float asq[4]  = {0.f, 0.f, 0.f, 0.f};

    float4 pa0, pa1;
    // prologue: chunk 0
    pa0 = *(const float4*)(xb + (size_t)k0 * 4096 + f40 * 4);
    pa1 = *(const float4*)(xb + (size_t)k1 * 4096 + f41 * 4);
    cp_async16(sbase + BS_OFF + (k0 * 128 + f40 * 4) * 4, Wf + (size_t)k0 * 768 + j0 + f40 * 4);
    cp_async16(sbase + BS_OFF + (k1 * 128 + f41 * 4) * 4, Wf + (size_t)k1 * 768 + j0 + f41 * 4);
    CP_COMMIT();
    asum[0] += pa0.x + pa1.x; asq[0] += pa0.x * pa0.x + pa1.x * pa1.x;
    asum[1] += pa0.y + pa1.y; asq[1] += pa0.y * pa0.y + pa1.y * pa1.y;
    asum[2] += pa0.z + pa1.z; asq[2] += pa0.z * pa0.z + pa1.z * pa1.z;
    asum[3] += pa0.w + pa1.w; asq[3] += pa0.w * pa0.w + pa1.w * pa1.w;
    {
        float* d0 = (float*)&Asd[0][k0][f40 * 4];
        *(float4*)d0       = make_float4(pa0.x, pa0.x, pa0.y, pa0.y);
        *(float4*)(d0 + 4) = make_float4(pa0.z, pa0.z, pa0.w, pa0.w);
        float* d1 = (float*)&Asd[0][k1][f41 * 4];
        *(float4*)d1       = make_float4(pa1.x, pa1.x, pa1.y, pa1.y);
        *(float4*)(d1 + 4) = make_float4(pa1.z, pa1.z, pa1.w, pa1.w);
    }

    int buf = 0;
    for (int c0 = 0; c0 < K; c0 += 16, buf ^= 1) {
        CP_WAIT0();
        __syncthreads();
        bool has_next = (c0 + 16 < K);
        if (has_next) {
            const float* xn = xb + (size_t)(c0 + 16) * 4096;
            pa0 = *(const float4*)(xn + (size_t)k0 * 4096 + f40 * 4);
            pa1 = *(const float4*)(xn + (size_t)k1 * 4096 + f41 * 4);
            uint32_t bdst = sbase + BS_OFF + (buf ^ 1) * 8192;
            const float* wn = Wf + (size_t)(c0 + 16) * 768 + j0;
            cp_async16(bdst + (k0 * 128 + f40 * 4) * 4, wn + (size_t)k0 * 768 + f40 * 4);
            cp_async16(bdst + (k1 * 128 + f41 * 4) * 4, wn + (size_t)k1 * 768 + f41 * 4);
            CP_COMMIT();
        }
        mma16(Asd[buf], Bs[buf], acc, tx, ty);
        if (has_next) {
            asum[0] += pa0.x + pa1.x; asq[0] += pa0.x * pa0.x + pa1.x * pa1.x;
            asum[1] += pa0.y + pa1.y; asq[1] += pa0.y * pa0.y + pa1.y * pa1.y;
            asum[2] += pa0.z + pa1.z; asq[2] += pa0.z * pa0.z + pa1.z * pa1.z;
            asum[3] += pa0.w + pa1.w; asq[3] += pa0.w * pa0.w + pa1.w * pa1.w;
            float* d0 = (float*)&Asd[buf ^ 1][k0][f40 * 4];
            *(float4*)d0       = make_float4(pa0.x, pa0.x, pa0.y, pa0.y);
            *(float4*)(d0 + 4) = make_float4(pa0.z, pa0.z, pa0.w, pa0.w);
            float* d1 = (float*)&Asd[buf ^ 1][k1][f41 * 4];
            *(float4*)d1       = make_float4(pa1.x, pa1.x, pa1.y, pa1.y);
            *(float4*)(d1 + 4) = make_float4(pa1.z, pa1.z, pa1.w, pa1.w);
        }
    }

    // ---- cross-thread LN-stat reduction through (now idle) smem ----
    __syncthreads();  // everyone done reading GEMM buffers
    float* ps  = (float*)smem;          // [8][128] partial sums
    float* pq  = ps + 1024;             // [8][128] partial sumsq
    float* muS = pq + 1024;             // [128]
    float* rsS = muS + 128;             // [128]
#pragma unroll
    for (int i = 0; i < 4; i++) {
        ps[k0 * 128 + f40 * 4 + i] = asum[i];
        pq[k0 * 128 + f40 * 4 + i] = asq[i];
    }
    __syncthreads();
    if (tid < 128) {
        float s = 0.f, q = 0.f;
#pragma unroll
        for (int r = 0; r < 8; r++) {
            s += ps[r * 128 + tid];
            q += pq[r * 128 + tid];
        }
        float m = s * (1.0f / K);
        float v = q * (1.0f / K) - m * m;
        muS[tid] = m;
        rsS[tid] = rsqrtf(v + EPSF);
    }
    __syncthreads();

    float cs[8], bv[8];
#pragma unroll
    for (int j = 0; j < 8; j++) {
        cs[j] = colsum[j0 + tx * 8 + j];
        bv[j] = bb[j0 + tx * 8 + j];
    }
#pragma unroll
    for (int i = 0; i < 8; i++) {
        int srow = ty * 8 + i;
        int s = s0 + srow;
        float r = rsS[srow], m = muS[srow];
        float c[8];
#pragma unroll
        for (int jj = 0; jj < 4; jj++) upk(acc[i][jj], c[2 * jj], c[2 * jj + 1]);
        float4 o0, o1;
        o0.x = r * (c[0] - m * cs[0]) + bv[0];
        o0.y = r * (c[1] - m * cs[1]) + bv[1];
        o0.z = r * (c[2] - m * cs[2]) + bv[2];
        o0.w = r * (c[3] - m * cs[3]) + bv[3];
        o1.x = r * (c[4] - m * cs[4]) + bv[4];
        o1.y = r * (c[5] - m * cs[5]) + bv[5];
        o1.z = r * (c[6] - m * cs[6]) + bv[6];
        o1.w = r * (c[7] - m * cs[7]) + bv[7];
        float* op = out + (size_t)s * 768 + j0 + tx * 8;
        *(float4*)op = o0;
        *(float4*)(op + 4) = o1;
    }
}

// ------------------------- 3) axial attention ----------------------------
__global__ __launch_bounds__(64)
void attn_kernel() {
    __shared__ __align__(16) float Ks[64][32];
    __shared__ __align__(16) float Vs[64][32];
    const int t = threadIdx.x;
    const int line = blockIdx.x;
    const int b = blockIdx.y >> 3, n = blockIdx.y & 7;
    const int br = blockIdx.z >> 1, dir = blockIdx.z & 1;

    const float* Qb  = br ? g_buf2 : g_buf1;
    const float* KVb = br ? g_buf1 : g_buf2;
    float* ob = br ? (dir ? g_o2c : g_o2r) : (dir ? g_o1c : g_o1r);

    int s_t = (dir == 0) ? (b * 4096 + t * 64 + line) : (b * 4096 + line * 64 + t);

    const float* qp = Qb  + (size_t)s_t * 768 + n * 32;
    const float* kp = KVb + (size_t)s_t * 768 + 256 + n * 32;
    const float* vp = kp + 256;
#pragma unroll
    for (int d4 = 0; d4 < 8; d4++) {
        *(float4*)&Ks[t][d4 * 4] = *(const float4*)(kp + d4 * 4);
        *(float4*)&Vs[t][d4 * 4] = *(const float4*)(vp + d4 * 4);
    }
    u64 q2[16];
#pragma unroll
    for (int d = 0; d < 16; d++) q2[d] = *(const u64*)(qp + 2 * d);
    __syncthreads();

    float sc[64];
    float smax = -1e30f;
#pragma unroll
    for (int j = 0; j < 64; j++) {
        const u64* k2 = (const u64*)Ks[j];
        u64 a = 0ULL;
#pragma unroll
        for (int d = 0; d < 16; d++) a = fma2(q2[d], k2[d], a);
        float lo, hi; upk(a, lo, hi);
        float v = (lo + hi) * 0.17677669529663687f;
        sc[j] = v;
        smax = fmaxf(smax, v);
    }
    float ssum = 0.f;
#pragma unroll
    for (int j = 0; j < 64; j++) {
        float e = __expf(sc[j] - smax);
        sc[j] = e;
        ssum += e;
    }
    float inv = 1.f / ssum;
    u64 o2[16];
#pragma unroll
    for (int d = 0; d < 16; d++) o2[d] = 0ULL;
#pragma unroll
    for (int j = 0; j < 64; j++) {
        u64 pd = dupf(sc[j]);
        const u64* v2 = (const u64*)Vs[j];
#pragma unroll
        for (int d = 0; d < 16; d++) o2[d] = fma2(pd, v2[d], o2[d]);
    }
    u64 iv = dupf(inv);
    float* op = ob + (size_t)s_t * 256 + n * 32;
#pragma unroll
    for (int d = 0; d < 16; d++) {
        u64 r = fma2(o2[d], iv, 0ULL);
        *(u64*)(op + 2 * d) = r;
    }
}

// ------------------------- 4) final fused GEMM (pipelined) ---------------
__global__ __launch_bounds__(256, 2)
void final_gemm_kernel(const float* __restrict__ x1, const float* __restrict__ x2,
                       const float* __restrict__ Wout1, const float* __restrict__ Wout2,
                       float* __restrict__ out) {
    extern __shared__ char smem[];
    u64 (*Asd)[16][130] = (u64(*)[16][130])smem;
    float (*Bs)[16][128] = (float(*)[16][128])(smem + BS_OFF);
    const uint32_t sbase = smem_u32(smem);

    const int tid = threadIdx.x;
    const int tx = tid & 15, ty = tid >> 4;
    const int s0 = blockIdx.y * 128;
    const int j0 = blockIdx.x * 128;
    const int b = s0 >> 12, p0 = s0 & 4095;

    const int k0 = tid >> 5, f40 = tid & 31;
    const int k1 = k0 + 8, f41 = f40;
    // row-major A staging map (phases B/C)
    const int row0 = tid >> 2, q0 = tid & 3;
    const int row1 = (tid + 256) >> 2, q1 = (tid + 256) & 3;

    u64 acc[8][4];
#pragma unroll
    for (int i = 0; i < 8; i++)
#pragma unroll
        for (int j = 0; j < 4; j++) acc[i][j] = 0ULL;

    int buf = 0;

    // ---------- Phase A: shortcut conv (x1 c-major @ g_Wscf), K = 384 ----
    {
        const float* xb = x1 + ((size_t)b * 384) * 4096 + p0;
        float4 pa0, pa1;
        pa0 = *(const float4*)(xb + (size_t)k0 * 4096 + f40 * 4);
        pa1 = *(const float4*)(xb + (size_t)k1 * 4096 + f41 * 4);
        cp_async16(sbase + BS_OFF + buf * 8192 + (k0 * 128 + f40 * 4) * 4,
                   g_Wscf + (size_t)k0 * 256 + j0 + f40 * 4);
        cp_async16(sbase + BS_OFF + buf * 8192 + (k1 * 128 + f41 * 4) * 4,
                   g_Wscf + (size_t)k1 * 256 + j0 + f41 * 4);
        CP_COMMIT();
        {
            float* d0 = (float*)&Asd[buf][k0][f40 * 4];
            *(float4*)d0       = make_float4(pa0.x, pa0.x, pa0.y, pa0.y);
            *(float4*)(d0 + 4) = make_float4(pa0.z, pa0.z, pa0.w, pa0.w);
            float* d1 = (float*)&Asd[buf][k1][f41 * 4];
            *(float4*)d1       = make_float4(pa1.x, pa1.x, pa1.y, pa1.y);
            *(float4*)(d1 + 4) = make_float4(pa1.z, pa1.z, pa1.w, pa1.w);
        }
        for (int c0 = 0; c0 < 384; c0 += 16, buf ^= 1) {
            CP_WAIT0();
            __syncthreads();
            bool has_next = (c0 + 16 < 384);
            if (has_next) {
                const float* xn = xb + (size_t)(c0 + 16) * 4096;
                pa0 = *(const float4*)(xn + (size_t)k0 * 4096 + f40 * 4);
                pa1 = *(const float4*)(xn + (size_t)k1 * 4096 + f41 * 4);
                uint32_t bdst = sbase + BS_OFF + (buf ^ 1) * 8192;
                const float* wn = g_Wscf + (size_t)(c0 + 16) * 256 + j0;
                cp_async16(bdst + (k0 * 128 + f40 * 4) * 4, wn + (size_t)k0 * 256 + f40 * 4);
                cp_async16(bdst + (k1 * 128 + f41 * 4) * 4, wn + (size_t)k1 * 256 + f41 * 4);
                CP_COMMIT();
            }
            mma16(Asd[buf], Bs[buf], acc, tx, ty);
            if (has_next) {
                float* d0 = (float*)&Asd[buf ^ 1][k0][f40 * 4];
                *(float4*)d0       = make_float4(pa0.x, pa0.x, pa0.y, pa0.y);
                *(float4*)(d0 + 4) = make_float4(pa0.z, pa0.z, pa0.w, pa0.w);
                float* d1 = (float*)&Asd[buf ^ 1][k1][f41 * 4];
                *(float4*)d1       = make_float4(pa1.x, pa1.x, pa1.y, pa1.y);
                *(float4*)(d1 + 4) = make_float4(pa1.z, pa1.z, pa1.w, pa1.w);
            }
        }
    }

    // ---------- Phases B/C: (o_r + o_c) @ Wout, K = 256 each -------------
#pragma unroll
    for (int ph = 0; ph < 2; ph++) {
        const float* o_r = ph ? g_o2r : g_o1r;
        const float* o_c = ph ? g_o2c : g_o1c;
        const float* W   = ph ? Wout2 : Wout1;

        float4 sa0, sa1;
        {
            float4 a = *(const float4*)(o_r + (size_t)(s0 + row0) * 256 + q0 * 4);
            float4 c = *(const float4*)(o_c + (size_t)(s0 + row0) * 256 + q0 * 4);
            sa0 = make_float4(a.x + c.x, a.y + c.y, a.z + c.z, a.w + c.w);
            a = *(const float4*)(o_r + (size_t)(s0 + row1) * 256 + q1 * 4);
            c = *(const float4*)(o_c + (size_t)(s0 + row1) * 256 + q1 * 4);
            sa1 = make_float4(a.x + c.x, a.y + c.y, a.z + c.z, a.w + c.w);
        }
        __syncthreads();  // previous phase readers done before overwriting buf
        cp_async16(sbase + BS_OFF + buf * 8192 + (k0 * 128 + f40 * 4) * 4,
                   W + (size_t)k0 * 256 + j0 + f40 * 4);
        cp_async16(sbase + BS_OFF + buf * 8192 + (k1 * 128 + f41 * 4) * 4,
                   W + (size_t)k1 * 256 + j0 + f41 * 4);
        CP_COMMIT();
        {
            Asd[buf][q0 * 4 + 0][row0] = dupf(sa0.x);
            Asd[buf][q0 * 4 + 1][row0] = dupf(sa0.y);
            Asd[buf][q0 * 4 + 2][row0] = dupf(sa0.z);
            Asd[buf][q0 * 4 + 3][row0] = dupf(sa0.w);
            Asd[buf][q1 * 4 + 0][row1] = dupf(sa1.x);
            Asd[buf][q1 * 4 + 1][row1] = dupf(sa1.y);
            Asd[buf][q1 * 4 + 2][row1] = dupf(sa1.z);
            Asd[buf][q1 * 4 + 3][row1] = dupf(sa1.w);
        }
        for (int c0 = 0; c0 < 256; c0 += 16, buf ^= 1) {
            CP_WAIT0();
            __syncthreads();
            bool has_next = (c0 + 16 < 256);
            if (has_next) {
                int cn = c0 + 16;
                float4 a = *(const float4*)(o_r + (size_t)(s0 + row0) * 256 + cn + q0 * 4);
                float4 c = *(const float4*)(o_c + (size_t)(s0 + row0) * 256 + cn + q0 * 4);
                sa0 = make_float4(a.x + c.x, a.y + c.y, a.z + c.z, a.w + c.w);
                a = *(const float4*)(o_r + (size_t)(s0 + row1) * 256 + cn + q1 * 4);
                c = *(const float4*)(o_c + (size_t)(s0 + row1) * 256 + cn + q1 * 4);
                sa1 = make_float4(a.x + c.x, a.y + c.y, a.z + c.z, a.w + c.w);
                uint32_t bdst = sbase + BS_OFF + (buf ^ 1) * 8192;
                const float* wn = W + (size_t)cn * 256 + j0;
                cp_async16(bdst + (k0 * 128 + f40 * 4) * 4, wn + (size_t)k0 * 256 + f40 * 4);
                cp_async16(bdst + (k1 * 128 + f41 * 4) * 4, wn + (size_t)k1 * 256 + f41 * 4);
                CP_COMMIT();
            }
            mma16(Asd[buf], Bs[buf], acc, tx, ty);
            if (has_next) {
                Asd[buf ^ 1][q0 * 4 + 0][row0] = dupf(sa0.x);
                Asd[buf ^ 1][q0 * 4 + 1][row0] = dupf(sa0.y);
                Asd[buf ^ 1][q0 * 4 + 2][row0] = dupf(sa0.z);
                Asd[buf ^ 1][q0 * 4 + 3][row0] = dupf(sa0.w);
                Asd[buf ^ 1][q1 * 4 + 0][row1] = dupf(sa1.x);
                Asd[buf ^ 1][q1 * 4 + 1][row1] = dupf(sa1.y);
                Asd[buf ^ 1][q1 * 4 + 2][row1] = dupf(sa1.z);
                Asd[buf ^ 1][q1 * 4 + 3][row1] = dupf(sa1.w);
            }
        }
    }

    // epilogue: bias + x2 residual, store NCHW
    float cf[8][8];
#pragma unroll
    for (int i = 0; i < 8; i++)
#pragma unroll
        for (int jj = 0; jj < 4; jj++) upk(acc[i][jj], cf[i][2 * jj], cf[i][2 * jj + 1]);

#pragma unroll
    for (int j = 0; j < 8; j++) {
        int o = j0 + tx * 8 + j;
        size_t base = ((size_t)(b * 256 + o)) * 4096 + p0 + ty * 8;
        float bt = g_btot[o];
        float4 xa  = *(const float4*)(x2 + base);
        float4 xb4 = *(const float4*)(x2 + base + 4);
        float4 r0, r1;
        r0.x = cf[0][j] + bt + xa.x;
        r0.y = cf[1][j] + bt + xa.y;
        r0.z = cf[2][j] + bt + xa.z;
        r0.w = cf[3][j] + bt + xa.w;
        r1.x = cf[4][j] + bt + xb4.x;
        r1.y = cf[5][j] + bt + xb4.y;
        r1.z = cf[6][j] + bt + xb4.z;
        r1.w = cf[7][j] + bt + xb4.w;
        *(float4*)(out + base) = r0;
        *(float4*)(out + base + 4) = r1;
    }
}

// ------------------------- launch ---------------------------------------
extern "C" void kernel_launch(void* const* d_in, const int* in_sizes, int n_in,
                              void* d_out, int out_size) {
    (void)in_sizes; (void)n_in; (void)out_size;
    const float* x1      = (const float*)d_in[0];
    const float* x2      = (const float*)d_in[1];
    const float* ln1q_w  = (const float*)d_in[2];
    const float* ln1q_b  = (const float*)d_in[3];
    const float* ln2kv_w = (const float*)d_in[4];
    const float* ln2kv_b = (const float*)d_in[5];
    const float* Wq1     = (const float*)d_in[6];
    const float* Wkv2    = (const float*)d_in[7];
    const float* Wout1   = (const float*)d_in[8];
    const float* bout1   = (const float*)d_in[9];
    const float* ln2q_w  = (const float*)d_in[10];
    const float* ln2q_b  = (const float*)d_in[11];
    const float* ln1kv_w = (const float*)d_in[12];
    const float* ln1kv_b = (const float*)d_in[13];
    const float* Wq2     = (const float*)d_in[14];
    const float* Wkv1    = (const float*)d_in[15];
    const float* Wout2   = (const float*)d_in[16];
    const float* bout2   = (const float*)d_in[17];
    const float* Wsc     = (const float*)d_in[18];
    const float* bn_g    = (const float*)d_in[19];
    const float* bn_b    = (const float*)d_in[20];
    const float* bn_m    = (const float*)d_in[21];
    const float* bn_v    = (const float*)d_in[22];
    float* out = (float*)d_out;

    cudaFuncSetAttribute(proj_gemm_kernel<0>, cudaFuncAttributeMaxDynamicSharedMemorySize, SMEM_GEMM_BYTES);
    cudaFuncSetAttribute(proj_gemm_kernel<1>, cudaFuncAttributeMaxDynamicSharedMemorySize, SMEM_GEMM_BYTES);
    cudaFuncSetAttribute(final_gemm_kernel,   cudaFuncAttributeMaxDynamicSharedMemorySize, SMEM_GEMM_BYTES);

    fold_w_kernel<<<1152, 256>>>(Wq1, Wkv1, ln1q_w, ln1kv_w,
                                 Wq2, Wkv2, ln2q_w, ln2kv_w,
                                 Wsc, bn_g, bn_v);
    fold_cols_kernel<<<768, 128>>>(Wq1, Wkv1, ln1q_b, ln1kv_b,
                                   Wq2, Wkv2, ln2q_b, ln2kv_b,
                                   bout1, bout2, bn_g, bn_b, bn_m, bn_v);
    proj_gemm_kernel<0><<<dim3(6, 256), 256, SMEM_GEMM_BYTES>>>(x1);
    proj_gemm_kernel<1><<<dim3(6, 256), 256, SMEM_GEMM_BYTES>>>(x2);
    attn_kernel<<<dim3(64, 64, 4), 64>>>();
    final_gemm_kernel<<<dim3(2, 256), 256, SMEM_GEMM_BYTES>>>(x1, x2, Wout1, Wout2, out);
}